// round 1
// baseline (speedup 1.0000x reference)
#include <cuda_runtime.h>

// ---------------------------------------------------------------------------
// SNNEmbeddingModel: B=8, S=128, D=512, N_in=N_out=1024, T=32, alpha=0.9
//
// Decomposition:
//   k1: snn_input = relu(emb @ W_in + b_in)                 [1024 x 1024], K=512
//   k2: per-(b,n) LIF scan over all 4096 steps -> s_in dense [32768 x 1024]
//   k3: I = s_in @ W_conn (dense fp32 GEMM, 68.7 GFLOP)      [32768 x 1024]
//   k4: per-(b,j) LIF scan over I -> spike_acc per position   [1024 x 1024]
//   k5: out = spike_acc @ W_out + b_out (+ spike_rate scalar) [1024 x 512]
// ---------------------------------------------------------------------------

namespace {
constexpr float kAlpha  = 0.9f;
constexpr float kThresh = 1.0f;
constexpr int kB = 8, kS = 128, kD = 512, kNin = 1024, kNout = 1024, kT = 32;
constexpr int kSteps = kS * kT;        // 4096
constexpr int kM     = kSteps * kB;    // 32768
}  // namespace

// Scratch (device globals; no allocation allowed in kernel_launch).
__device__ float g_snn[(size_t)kB * kS * kNin];    // [b*S+s][n]          4 MB
__device__ float g_sin[(size_t)kM * kNin];         // [(s*T+t)*B+b][n]  128 MB
__device__ float g_cur[(size_t)kM * kNout];        // currents          128 MB
__device__ float g_sacc[(size_t)kS * kB * kNout];  // [s*B+b][j]          4 MB
__device__ unsigned long long g_spk;

// ---------------------------------------------------------------------------
// k1: 64x64x16 tiled GEMM, 256 threads, 4x4 per thread. C = relu(A@W + bias).
// A = embeddings [1024 x 512], W = W_in [512 x 1024]. Also zeroes spike ctr.
// ---------------------------------------------------------------------------
__global__ void k1_gemm_in(const float* __restrict__ A, const float* __restrict__ W,
                           const float* __restrict__ bias) {
  if (blockIdx.x == 0 && blockIdx.y == 0 && threadIdx.x == 0) g_spk = 0ull;

  __shared__ float As[16][66];   // padded: conflict-free transposed stores
  __shared__ float Bs[16][64];
  const int tid = threadIdx.x;
  const int bm = blockIdx.y * 64, bn = blockIdx.x * 64;
  const int tr = (tid >> 4) * 4, tc = (tid & 15) * 4;
  const int arow = tid >> 2,  ak   = (tid & 3) * 4;
  const int brow = tid >> 4,  bcol = (tid & 15) * 4;

  float acc[4][4] = {};
  for (int kk = 0; kk < kD; kk += 16) {
    float4 av = *reinterpret_cast<const float4*>(&A[(size_t)(bm + arow) * kD + kk + ak]);
    float4 bv = *reinterpret_cast<const float4*>(&W[(size_t)(kk + brow) * kNin + bn + bcol]);
    As[ak + 0][arow] = av.x; As[ak + 1][arow] = av.y;
    As[ak + 2][arow] = av.z; As[ak + 3][arow] = av.w;
    *reinterpret_cast<float4*>(&Bs[brow][bcol]) = bv;
    __syncthreads();
#pragma unroll
    for (int k = 0; k < 16; k++) {
      float a[4], b[4];
#pragma unroll
      for (int i = 0; i < 4; i++) a[i] = As[k][tr + i];
#pragma unroll
      for (int j = 0; j < 4; j++) b[j] = Bs[k][tc + j];
#pragma unroll
      for (int i = 0; i < 4; i++)
#pragma unroll
        for (int j = 0; j < 4; j++) acc[i][j] = fmaf(a[i], b[j], acc[i][j]);
    }
    __syncthreads();
  }
#pragma unroll
  for (int i = 0; i < 4; i++)
#pragma unroll
    for (int j = 0; j < 4; j++) {
      const int n = bn + tc + j;
      g_snn[(size_t)(bm + tr + i) * kNin + n] = fmaxf(acc[i][j] + bias[n], 0.0f);
    }
}

// ---------------------------------------------------------------------------
// k2: input-population LIF. One thread per (b, n); walks all S*T steps.
// Writes dense s_in in GEMM row order m = (s*T+t)*B + b (coalesced in n).
// ---------------------------------------------------------------------------
__global__ void k2_vin() {
  const int id = blockIdx.x * blockDim.x + threadIdx.x;  // 8192 threads
  const int b = id >> 10, n = id & 1023;
  float v = 0.0f;
  unsigned cnt = 0;
  for (int s = 0; s < kS; s++) {
    const float x = g_snn[(size_t)(b * kS + s) * kNin + n];
    const size_t base = ((size_t)(s * kT) * kB + b) * kNin + n;
#pragma unroll
    for (int t = 0; t < kT; t++) {
      v = fmaf(kAlpha, v, x);
      const bool f = (v >= kThresh);
      const float sp = f ? 1.0f : 0.0f;
      cnt += f;
      v -= sp;
      g_sin[base + (size_t)t * (kB * kNin)] = sp;
    }
  }
  atomicAdd(&g_spk, (unsigned long long)cnt);
}

// ---------------------------------------------------------------------------
// k3: big GEMM. C[32768 x 1024] = s_in @ W_conn. 128x128x8 tiles, 256 thr,
// 8x8 per thread, register prefetch of next k-slab. ~68.7 GFLOP fp32.
// ---------------------------------------------------------------------------
__global__ void __launch_bounds__(256) k3_gemm_conn(const float* __restrict__ W) {
  __shared__ float As[8][132];   // padded, stored transposed
  __shared__ float Bs[8][128];
  const int tid = threadIdx.x;
  const int bm = blockIdx.y * 128, bn = blockIdx.x * 128;
  const int tr = (tid >> 4) * 8, tc = (tid & 15) * 8;
  const int arow = tid >> 1,  ak   = (tid & 1) * 4;
  const int brow = tid >> 5,  bcol = (tid & 31) * 4;

  const float* Ap = &g_sin[(size_t)(bm + arow) * kNin + ak];          // + kk
  const float* Bp = &W[(size_t)brow * kNout + bn + bcol];             // + kk*N

  float acc[8][8] = {};
  float4 av = *reinterpret_cast<const float4*>(Ap);
  float4 bv = *reinterpret_cast<const float4*>(Bp);

  for (int kk = 0; kk < kNin; kk += 8) {
    As[ak + 0][arow] = av.x; As[ak + 1][arow] = av.y;
    As[ak + 2][arow] = av.z; As[ak + 3][arow] = av.w;
    *reinterpret_cast<float4*>(&Bs[brow][bcol]) = bv;
    __syncthreads();
    if (kk + 8 < kNin) {   // prefetch next slab while this one computes
      av = *reinterpret_cast<const float4*>(Ap + kk + 8);
      bv = *reinterpret_cast<const float4*>(Bp + (size_t)(kk + 8) * kNout);
    }
#pragma unroll
    for (int k = 0; k < 8; k++) {
      float a[8], b[8];
#pragma unroll
      for (int i = 0; i < 8; i++) a[i] = As[k][tr + i];
#pragma unroll
      for (int j = 0; j < 8; j++) b[j] = Bs[k][tc + j];
#pragma unroll
      for (int i = 0; i < 8; i++)
#pragma unroll
        for (int j = 0; j < 8; j++) acc[i][j] = fmaf(a[i], b[j], acc[i][j]);
    }
    __syncthreads();
  }
#pragma unroll
  for (int i = 0; i < 8; i++) {
    float* crow = &g_cur[(size_t)(bm + tr + i) * kNout + bn + tc];
#pragma unroll
    for (int j = 0; j < 8; j += 4)
      *reinterpret_cast<float4*>(crow + j) =
          make_float4(acc[i][j], acc[i][j + 1], acc[i][j + 2], acc[i][j + 3]);
  }
}

// ---------------------------------------------------------------------------
// k4: output-population LIF. One thread per (b, j); reads precomputed
// currents (coalesced), accumulates per-position spike counts.
// ---------------------------------------------------------------------------
__global__ void k4_vout() {
  const int id = blockIdx.x * blockDim.x + threadIdx.x;  // 8192 threads
  const int b = id >> 10, j = id & 1023;
  float v = 0.0f;
  unsigned cnt = 0;
  for (int s = 0; s < kS; s++) {
    float acc = 0.0f;
    const size_t base = ((size_t)(s * kT) * kB + b) * kNout + j;
#pragma unroll
    for (int t = 0; t < kT; t++) {
      const float I = g_cur[base + (size_t)t * (kB * kNout)];
      v = fmaf(kAlpha, v, I);
      const bool f = (v >= kThresh);
      const float sp = f ? 1.0f : 0.0f;
      acc += sp;
      cnt += f;
      v -= sp;
    }
    g_sacc[(size_t)(s * kB + b) * kNout + j] = acc;
  }
  atomicAdd(&g_spk, (unsigned long long)cnt);
}

// ---------------------------------------------------------------------------
// k5: out = spike_acc @ W_out + b_out, permuted store to [b][s][d].
// 64x64x16 tiles. Row m = s*B + b. Also writes spike_rate scalar.
// ---------------------------------------------------------------------------
__global__ void k5_gemm_out(const float* __restrict__ W, const float* __restrict__ bias,
                            float* __restrict__ out, int write_rate) {
  if (write_rate && blockIdx.x == 0 && blockIdx.y == 0 && threadIdx.x == 0) {
    // denominator: B*S*(N_in+N_out)*T = 2^26
    out[(size_t)kB * kS * kD] =
        (float)((double)g_spk / (double)((size_t)kB * kS * (kNin + kNout) * kT));
  }
  __shared__ float As[16][66];
  __shared__ float Bs[16][64];
  const int tid = threadIdx.x;
  const int bm = blockIdx.y * 64, bn = blockIdx.x * 64;
  const int tr = (tid >> 4) * 4, tc = (tid & 15) * 4;
  const int arow = tid >> 2,  ak   = (tid & 3) * 4;
  const int brow = tid >> 4,  bcol = (tid & 15) * 4;

  float acc[4][4] = {};
  for (int kk = 0; kk < kNout; kk += 16) {
    float4 av = *reinterpret_cast<const float4*>(&g_sacc[(size_t)(bm + arow) * kNout + kk + ak]);
    float4 bv = *reinterpret_cast<const float4*>(&W[(size_t)(kk + brow) * kD + bn + bcol]);
    As[ak + 0][arow] = av.x; As[ak + 1][arow] = av.y;
    As[ak + 2][arow] = av.z; As[ak + 3][arow] = av.w;
    *reinterpret_cast<float4*>(&Bs[brow][bcol]) = bv;
    __syncthreads();
#pragma unroll
    for (int k = 0; k < 16; k++) {
      float a[4], b[4];
#pragma unroll
      for (int i = 0; i < 4; i++) a[i] = As[k][tr + i];
#pragma unroll
      for (int j = 0; j < 4; j++) b[j] = Bs[k][tc + j];
#pragma unroll
      for (int i = 0; i < 4; i++)
#pragma unroll
        for (int j = 0; j < 4; j++) acc[i][j] = fmaf(a[i], b[j], acc[i][j]);
    }
    __syncthreads();
  }
#pragma unroll
  for (int i = 0; i < 4; i++) {
    const int m = bm + tr + i;
    const int s = m >> 3;       // rows are m = s*B + b
    const int b = m & 7;
#pragma unroll
    for (int j = 0; j < 4; j++) {
      const int n = bn + tc + j;
      out[((size_t)(b * kS + s)) * kD + n] = acc[i][j] + bias[n];
    }
  }
}

// ---------------------------------------------------------------------------
extern "C" void kernel_launch(void* const* d_in, const int* in_sizes, int n_in,
                              void* d_out, int out_size) {
  const float* emb    = (const float*)d_in[0];
  const float* W_in   = (const float*)d_in[1];
  const float* b_in   = (const float*)d_in[2];
  const float* W_conn = (const float*)d_in[3];
  const float* W_out  = (const float*)d_in[4];
  const float* b_out  = (const float*)d_in[5];
  float* out = (float*)d_out;
  const int write_rate = (out_size > kB * kS * kD) ? 1 : 0;

  k1_gemm_in<<<dim3(kNin / 64, (kB * kS) / 64), 256>>>(emb, W_in, b_in);
  k2_vin<<<64, 128>>>();
  k3_gemm_conn<<<dim3(kNout / 128, kM / 128), 256>>>(W_conn);
  k4_vout<<<64, 128>>>();
  k5_gemm_out<<<dim3(kD / 64, (kS * kB) / 64), 256>>>(W_out, b_out, out, write_rate);
}

// round 2
// speedup vs baseline: 1.7987x; 1.7987x over previous
#include <cuda_runtime.h>
#include <cuda_bf16.h>
#include <cstdint>

// ---------------------------------------------------------------------------
// SNNEmbeddingModel: B=8, S=128, D=512, N_in=N_out=1024, T=32, alpha=0.9
//
//   k0: W_conn -> bf16 hi/lo pair, stored in mma B-fragment order (L2-resident)
//   k1: snn_input = relu(emb @ W_in + b_in)            fp32 SIMT GEMM (small)
//   k2: input LIF scan -> s_in spikes, bf16, stored in mma A-fragment order
//   k3: I = s_in @ (W_hi + W_lo)  via mma.sync.m16n8k16 (tensor cores, fp32 acc)
//   k4: output LIF scan over I (32-deep prefetch pipeline) -> spike_acc
//   k5: out = spike_acc @ W_out + b_out (+ spike_rate scalar)
// ---------------------------------------------------------------------------

namespace {
constexpr float kAlpha  = 0.9f;
constexpr float kThresh = 1.0f;
constexpr int kB = 8, kS = 128, kD = 512, kNin = 1024, kNout = 1024, kT = 32;
constexpr int kSteps = kS * kT;        // 4096
constexpr int kM     = kSteps * kB;    // 32768 GEMM rows, m = u*8 + b
constexpr int kKT    = kNin / 16;      // 64 k16 tiles
}  // namespace

// Scratch (device globals; no allocs allowed).
__device__ float g_snn[(size_t)kB * kS * kNin];                     //   4 MB
__device__ __align__(16) __nv_bfloat16 g_sin[(size_t)kM * kNin];    //  64 MB, A-frag order
__device__ __align__(16) __nv_bfloat16 g_Bhi[(size_t)kNin * kNout]; //   2 MB, B-frag order
__device__ __align__(16) __nv_bfloat16 g_Blo[(size_t)kNin * kNout]; //   2 MB, B-frag order
__device__ float g_cur[(size_t)kM * kNout];                         // 128 MB
__device__ float g_sacc[(size_t)kS * kB * kNout];                   //   4 MB
__device__ unsigned long long g_spk;

// ---------------------------------------------------------------------------
// k0: split W_conn into bf16 hi/lo, store in m16n8k16 B-fragment order.
// B frag (16k x 8n): lane = 4*n + (k&7)/2 ; slot = (k&1) + 2*((k>>3)&1).
// Also zeroes the spike counter.
// ---------------------------------------------------------------------------
__global__ void k0_prep(const float* __restrict__ W) {
  const int idx = blockIdx.x * blockDim.x + threadIdx.x;  // over 1M elements
  if (idx == 0) g_spk = 0ull;
  const int k = idx >> 10, n = idx & 1023;
  const float w = W[idx];
  const __nv_bfloat16 hi = __float2bfloat16(w);
  const __nv_bfloat16 lo = __float2bfloat16(w - __bfloat162float(hi));
  const int n8 = n >> 3, kk = k >> 4;
  const int lane = 4 * (n & 7) + ((k & 7) >> 1);
  const int slot = (k & 1) + 2 * ((k >> 3) & 1);
  const size_t off = ((size_t)n8 * kKT + kk) * 128 + lane * 4 + slot;
  g_Bhi[off] = hi;
  g_Blo[off] = lo;
}

// ---------------------------------------------------------------------------
// k1: 64x64x16 tiled fp32 GEMM, C = relu(emb @ W_in + b_in). [1024x1024] K=512.
// ---------------------------------------------------------------------------
__global__ void k1_gemm_in(const float* __restrict__ A, const float* __restrict__ W,
                           const float* __restrict__ bias) {
  __shared__ float As[16][66];
  __shared__ float Bs[16][64];
  const int tid = threadIdx.x;
  const int bm = blockIdx.y * 64, bn = blockIdx.x * 64;
  const int tr = (tid >> 4) * 4, tc = (tid & 15) * 4;
  const int arow = tid >> 2,  ak   = (tid & 3) * 4;
  const int brow = tid >> 4,  bcol = (tid & 15) * 4;

  float acc[4][4] = {};
  for (int kk = 0; kk < kD; kk += 16) {
    float4 av = *reinterpret_cast<const float4*>(&A[(size_t)(bm + arow) * kD + kk + ak]);
    float4 bv = *reinterpret_cast<const float4*>(&W[(size_t)(kk + brow) * kNin + bn + bcol]);
    As[ak + 0][arow] = av.x; As[ak + 1][arow] = av.y;
    As[ak + 2][arow] = av.z; As[ak + 3][arow] = av.w;
    *reinterpret_cast<float4*>(&Bs[brow][bcol]) = bv;
    __syncthreads();
#pragma unroll
    for (int k = 0; k < 16; k++) {
      float a[4], b[4];
#pragma unroll
      for (int i = 0; i < 4; i++) a[i] = As[k][tr + i];
#pragma unroll
      for (int j = 0; j < 4; j++) b[j] = Bs[k][tc + j];
#pragma unroll
      for (int i = 0; i < 4; i++)
#pragma unroll
        for (int j = 0; j < 4; j++) acc[i][j] = fmaf(a[i], b[j], acc[i][j]);
    }
    __syncthreads();
  }
#pragma unroll
  for (int i = 0; i < 4; i++)
#pragma unroll
    for (int j = 0; j < 4; j++) {
      const int n = bn + tc + j;
      g_snn[(size_t)(bm + tr + i) * kNin + n] = fmaxf(acc[i][j] + bias[n], 0.0f);
    }
}

// ---------------------------------------------------------------------------
// k2: input-population LIF. Thread per (b, n). Spikes stored bf16 in
// m16n8k16 A-fragment order. For row m = u*8 + b (u = global step):
//   rho = m&15 -> rho&7 = b, rho>>3 = u&1 ; tile_m = u>>1.
//   lane = 4*b + ((n&7)>>1) (per-thread const)
//   slot = (n&1) + 4*((n>>3)&1) + 2*(u&1)
// ---------------------------------------------------------------------------
__global__ void k2_vin() {
  const int id = blockIdx.x * blockDim.x + threadIdx.x;  // 8192
  const int b = id >> 10, n = id & 1023;
  const int tile_k = n >> 4;
  const int kap = n & 15;
  const int lane = 4 * b + ((kap & 7) >> 1);
  const int slot_base = (kap & 1) + 4 * (kap >> 3);
  float v = 0.0f;
  unsigned cnt = 0;
  for (int s = 0; s < kS; s++) {
    const float x = g_snn[(size_t)(b * kS + s) * kNin + n];
    const int u0 = s * kT;
#pragma unroll
    for (int t = 0; t < kT; t++) {
      const int u = u0 + t;
      v = fmaf(kAlpha, v, x);
      const bool f = (v >= kThresh);
      const float sp = f ? 1.0f : 0.0f;
      cnt += f;
      v -= sp;
      const size_t frag = (size_t)(u >> 1) * kKT + tile_k;
      g_sin[frag * 256 + lane * 8 + slot_base + 2 * (u & 1)] = __float2bfloat16(sp);
    }
  }
  atomicAdd(&g_spk, (unsigned long long)cnt);
}

// ---------------------------------------------------------------------------
// k3: tensor-core GEMM. C[32768 x 1024] = s_in @ (W_hi + W_lo), fp32 acc.
// Block 256 thr (8 warps, 2m x 4n), block tile 128x128, warp tile 64x32.
// Operands LDG'd directly in fragment order (no smem).
// ---------------------------------------------------------------------------
__device__ __forceinline__ void mma16816(float* c, const uint4& a, const uint2& b) {
  asm volatile(
      "mma.sync.aligned.m16n8k16.row.col.f32.bf16.bf16.f32 "
      "{%0,%1,%2,%3}, {%4,%5,%6,%7}, {%8,%9}, {%0,%1,%2,%3};"
      : "+f"(c[0]), "+f"(c[1]), "+f"(c[2]), "+f"(c[3])
      : "r"(a.x), "r"(a.y), "r"(a.z), "r"(a.w), "r"(b.x), "r"(b.y));
}

__global__ void __launch_bounds__(256, 2) k3_gemm_conn() {
  const int tid = threadIdx.x, wid = tid >> 5, lane = tid & 31;
  const int wm = wid >> 2, wn = wid & 3;
  const int m0 = blockIdx.y * 128 + wm * 64;
  const int n0 = blockIdx.x * 128 + wn * 32;
  const uint4* Af = reinterpret_cast<const uint4*>(g_sin);   // frag = 32 uint4
  const uint2* Bh = reinterpret_cast<const uint2*>(g_Bhi);   // frag = 32 uint2
  const uint2* Bl = reinterpret_cast<const uint2*>(g_Blo);
  const int mt0 = m0 >> 4;   // m16 tile base
  const int nt0 = n0 >> 3;   // n8 tile base

  float acc[4][4][4] = {};
  for (int kk = 0; kk < kKT; kk++) {
    uint4 a[4];
    uint2 bh[4], bl[4];
#pragma unroll
    for (int i = 0; i < 4; i++)
      a[i] = Af[((size_t)(mt0 + i) * kKT + kk) * 32 + lane];
#pragma unroll
    for (int j = 0; j < 4; j++) {
      bh[j] = Bh[((size_t)(nt0 + j) * kKT + kk) * 32 + lane];
      bl[j] = Bl[((size_t)(nt0 + j) * kKT + kk) * 32 + lane];
    }
#pragma unroll
    for (int i = 0; i < 4; i++)
#pragma unroll
      for (int j = 0; j < 4; j++) {
        mma16816(acc[i][j], a[i], bh[j]);
        mma16816(acc[i][j], a[i], bl[j]);
      }
  }
  const int g = lane >> 2, tg = lane & 3;
#pragma unroll
  for (int i = 0; i < 4; i++) {
    const int r = m0 + i * 16 + g;
#pragma unroll
    for (int j = 0; j < 4; j++) {
      const int c = n0 + j * 8 + tg * 2;
      *reinterpret_cast<float2*>(&g_cur[(size_t)r * kNout + c]) =
          make_float2(acc[i][j][0], acc[i][j][1]);
      *reinterpret_cast<float2*>(&g_cur[(size_t)(r + 8) * kNout + c]) =
          make_float2(acc[i][j][2], acc[i][j][3]);
    }
  }
}

// ---------------------------------------------------------------------------
// k4: output-population LIF, thread per (b, j). 32-deep double-buffered
// register prefetch (one position per chunk) for DRAM MLP.
// ---------------------------------------------------------------------------
__global__ void k4_vout() {
  const int id = blockIdx.x * blockDim.x + threadIdx.x;  // 8192
  const int b = id >> 10, j = id & 1023;
  const float* p = &g_cur[(size_t)b * kNout + j];
  const size_t stride = (size_t)kB * kNout;  // per step u
  float buf[2][kT];
#pragma unroll
  for (int t = 0; t < kT; t++) buf[0][t] = p[(size_t)t * stride];
  float v = 0.0f;
  unsigned cnt = 0;
  for (int s = 0; s < kS; s++) {
    const int cur = s & 1;
    if (s + 1 < kS) {
      const float* q = p + (size_t)(s + 1) * kT * stride;
#pragma unroll
      for (int t = 0; t < kT; t++) buf[cur ^ 1][t] = q[(size_t)t * stride];
    }
    float acc = 0.0f;
#pragma unroll
    for (int t = 0; t < kT; t++) {
      v = fmaf(kAlpha, v, buf[cur][t]);
      const bool f = (v >= kThresh);
      const float sp = f ? 1.0f : 0.0f;
      acc += sp;
      cnt += f;
      v -= sp;
    }
    g_sacc[(size_t)(s * kB + b) * kNout + j] = acc;
  }
  atomicAdd(&g_spk, (unsigned long long)cnt);
}

// ---------------------------------------------------------------------------
// k5: out = spike_acc @ W_out + b_out, permuted store to [b][s][d].
// ---------------------------------------------------------------------------
__global__ void k5_gemm_out(const float* __restrict__ W, const float* __restrict__ bias,
                            float* __restrict__ out, int write_rate) {
  if (write_rate && blockIdx.x == 0 && blockIdx.y == 0 && threadIdx.x == 0) {
    out[(size_t)kB * kS * kD] =
        (float)((double)g_spk / (double)((size_t)kB * kS * (kNin + kNout) * kT));
  }
  __shared__ float As[16][66];
  __shared__ float Bs[16][64];
  const int tid = threadIdx.x;
  const int bm = blockIdx.y * 64, bn = blockIdx.x * 64;
  const int tr = (tid >> 4) * 4, tc = (tid & 15) * 4;
  const int arow = tid >> 2,  ak   = (tid & 3) * 4;
  const int brow = tid >> 4,  bcol = (tid & 15) * 4;

  float acc[4][4] = {};
  for (int kk = 0; kk < kNout; kk += 16) {
    float4 av = *reinterpret_cast<const float4*>(&g_sacc[(size_t)(bm + arow) * kNout + kk + ak]);
    float4 bv = *reinterpret_cast<const float4*>(&W[(size_t)(kk + brow) * kD + bn + bcol]);
    As[ak + 0][arow] = av.x; As[ak + 1][arow] = av.y;
    As[ak + 2][arow] = av.z; As[ak + 3][arow] = av.w;
    *reinterpret_cast<float4*>(&Bs[brow][bcol]) = bv;
    __syncthreads();
#pragma unroll
    for (int k = 0; k < 16; k++) {
      float a[4], b[4];
#pragma unroll
      for (int i = 0; i < 4; i++) a[i] = As[k][tr + i];
#pragma unroll
      for (int j = 0; j < 4; j++) b[j] = Bs[k][tc + j];
#pragma unroll
      for (int i = 0; i < 4; i++)
#pragma unroll
        for (int j = 0; j < 4; j++) acc[i][j] = fmaf(a[i], b[j], acc[i][j]);
    }
    __syncthreads();
  }
#pragma unroll
  for (int i = 0; i < 4; i++) {
    const int m = bm + tr + i;
    const int s = m >> 3;   // rows are m = s*B + b
    const int b = m & 7;
#pragma unroll
    for (int j = 0; j < 4; j++) {
      const int n = bn + tc + j;
      out[((size_t)(b * kS + s)) * kD + n] = acc[i][j] + bias[n];
    }
  }
}

// ---------------------------------------------------------------------------
extern "C" void kernel_launch(void* const* d_in, const int* in_sizes, int n_in,
                              void* d_out, int out_size) {
  const float* emb    = (const float*)d_in[0];
  const float* W_in   = (const float*)d_in[1];
  const float* b_in   = (const float*)d_in[2];
  const float* W_conn = (const float*)d_in[3];
  const float* W_out  = (const float*)d_in[4];
  const float* b_out  = (const float*)d_in[5];
  float* out = (float*)d_out;
  const int write_rate = (out_size > kB * kS * kD) ? 1 : 0;

  k0_prep<<<(kNin * kNout) / 256, 256>>>(W_conn);
  k1_gemm_in<<<dim3(kNin / 64, (kB * kS) / 64), 256>>>(emb, W_in, b_in);
  k2_vin<<<64, 128>>>();
  k3_gemm_conn<<<dim3(kNout / 128, kM / 128), 256>>>();
  k4_vout<<<64, 128>>>();
  k5_gemm_out<<<dim3(kD / 64, (kS * kB) / 64), 256>>>(W_out, b_out, out, write_rate);
}

// round 4
// speedup vs baseline: 2.4243x; 1.3478x over previous
#include <cuda_runtime.h>
#include <cuda_fp16.h>
#include <cstdint>

// ---------------------------------------------------------------------------
// SNNEmbeddingModel: B=8, S=128, D=512, N_in=N_out=1024, T=32, alpha=0.9
//
//   k0: W_conn -> fp16 {lo*2^11, hi} planes, transposed to [n][k]
//   k1: snn_input = relu(emb @ W_in + b_in)            fp32 SIMT GEMM (small)
//   k2: input LIF scan -> s_in fp16, row-major [m][k], m = u*8+b
//   k3: I = s_in @ W^T via mma.sync m16n8k16 fp16, cp.async 3-stage pipeline,
//       acc = 2^-11 * (s@lo') + s@hi   (fp32-equivalent weights, 2 passes)
//   k4: output LIF scan over I (32-deep prefetch) -> spike_acc
//   k5: out = spike_acc @ W_out + b_out (+ spike_rate scalar)
// ---------------------------------------------------------------------------

namespace {
constexpr float kAlpha  = 0.9f;
constexpr float kThresh = 1.0f;
constexpr int kB = 8, kS = 128, kD = 512, kNin = 1024, kNout = 1024, kT = 32;
constexpr int kM = kS * kT * kB;          // 32768 rows, m = u*8 + b
constexpr int BM = 128, BN = 128, BK = 64, STAGES = 3;
constexpr int kStageBytes = (BM * BK + BN * BK) * 2;     // 32 KB
constexpr int kSmemK3 = STAGES * kStageBytes;            // 96 KB
constexpr int kKIters = 2 * (kNin / BK);                 // 32 (lo pass + hi pass)
}  // namespace

// Scratch (device globals; no allocation allowed).
__device__ float g_snn[(size_t)kB * kS * kNin];                   //   4 MB
__device__ __align__(16) __half g_sin[(size_t)kM * kNin];         //  64 MB
__device__ __align__(16) __half g_Wt[2][(size_t)kNout * kNin];    //   4 MB
__device__ float g_cur[(size_t)kM * kNout];                       // 128 MB
__device__ float g_sacc[(size_t)kS * kB * kNout];                 //   4 MB
__device__ unsigned long long g_spk;

// ------------------------------- helpers ----------------------------------
__device__ __forceinline__ uint32_t smem_u32(const void* p) {
  uint32_t a;
  asm("{ .reg .u64 t; cvta.to.shared.u64 t, %1; cvt.u32.u64 %0, t; }"
      : "=r"(a) : "l"(p));
  return a;
}
__device__ __forceinline__ uint32_t swz128(uint32_t off) {
  return off ^ ((off >> 3) & 0x70);   // 16B-chunk xor within 128B rows
}
__device__ __forceinline__ void cp_async16(uint32_t dst, const void* src) {
  asm volatile("cp.async.cg.shared.global [%0], [%1], 16;"
               :: "r"(dst), "l"(src) : "memory");
}
__device__ __forceinline__ void ldsm_x4(uint32_t* r, uint32_t addr) {
  asm volatile("ldmatrix.sync.aligned.m8n8.x4.shared.b16 {%0,%1,%2,%3}, [%4];"
               : "=r"(r[0]), "=r"(r[1]), "=r"(r[2]), "=r"(r[3]) : "r"(addr));
}
__device__ __forceinline__ void mma16816(float* c, const uint32_t* a,
                                         const uint32_t* b) {
  asm volatile(
      "mma.sync.aligned.m16n8k16.row.col.f32.f16.f16.f32 "
      "{%0,%1,%2,%3}, {%4,%5,%6,%7}, {%8,%9}, {%0,%1,%2,%3};"
      : "+f"(c[0]), "+f"(c[1]), "+f"(c[2]), "+f"(c[3])
      : "r"(a[0]), "r"(a[1]), "r"(a[2]), "r"(a[3]), "r"(b[0]), "r"(b[1]));
}

// ---------------------------------------------------------------------------
// k0: smem-tiled transpose + fp16 {lo*2^11, hi} split of W_conn [k][n].
// ---------------------------------------------------------------------------
__global__ void k0_prep(const float* __restrict__ W) {
  __shared__ float t[32][33];
  const int tx = threadIdx.x, ty = threadIdx.y;  // (32, 8)
  const int n0 = blockIdx.x * 32, k0 = blockIdx.y * 32;
  if (blockIdx.x == 0 && blockIdx.y == 0 && tx == 0 && ty == 0) g_spk = 0ull;
#pragma unroll
  for (int i = ty; i < 32; i += 8)
    t[i][tx] = W[(size_t)(k0 + i) * kNout + n0 + tx];
  __syncthreads();
#pragma unroll
  for (int i = ty; i < 32; i += 8) {
    const int n = n0 + i, k = k0 + tx;
    const float w = t[tx][i];
    const __half hi = __float2half_rn(w);
    const __half lo = __float2half_rn((w - __half2float(hi)) * 2048.0f);
    const size_t off = (size_t)n * kNin + k;
    g_Wt[0][off] = lo;   // pass 0: scaled residual
    g_Wt[1][off] = hi;   // pass 1: main term
  }
}

// ---------------------------------------------------------------------------
// k1: 64x64x16 tiled fp32 GEMM, C = relu(emb @ W_in + b_in). [1024x1024] K=512.
// ---------------------------------------------------------------------------
__global__ void k1_gemm_in(const float* __restrict__ A, const float* __restrict__ W,
                           const float* __restrict__ bias) {
  __shared__ float As[16][66];
  __shared__ float Bs[16][64];
  const int tid = threadIdx.x;
  const int bm = blockIdx.y * 64, bn = blockIdx.x * 64;
  const int tr = (tid >> 4) * 4, tc = (tid & 15) * 4;
  const int arow = tid >> 2, ak = (tid & 3) * 4;
  const int brow = tid >> 4, bcol = (tid & 15) * 4;

  float acc[4][4] = {};
  for (int kk = 0; kk < kD; kk += 16) {
    float4 av = *reinterpret_cast<const float4*>(&A[(size_t)(bm + arow) * kD + kk + ak]);
    float4 bv = *reinterpret_cast<const float4*>(&W[(size_t)(kk + brow) * kNin + bn + bcol]);
    As[ak + 0][arow] = av.x; As[ak + 1][arow] = av.y;
    As[ak + 2][arow] = av.z; As[ak + 3][arow] = av.w;
    *reinterpret_cast<float4*>(&Bs[brow][bcol]) = bv;
    __syncthreads();
#pragma unroll
    for (int k = 0; k < 16; k++) {
      float a[4], b[4];
#pragma unroll
      for (int i = 0; i < 4; i++) a[i] = As[k][tr + i];
#pragma unroll
      for (int j = 0; j < 4; j++) b[j] = Bs[k][tc + j];
#pragma unroll
      for (int i = 0; i < 4; i++)
#pragma unroll
        for (int j = 0; j < 4; j++) acc[i][j] = fmaf(a[i], b[j], acc[i][j]);
    }
    __syncthreads();
  }
#pragma unroll
  for (int i = 0; i < 4; i++)
#pragma unroll
    for (int j = 0; j < 4; j++) {
      const int n = bn + tc + j;
      g_snn[(size_t)(bm + tr + i) * kNin + n] = fmaxf(acc[i][j] + bias[n], 0.0f);
    }
}

// ---------------------------------------------------------------------------
// k2: input LIF. Thread per (b, n); coalesced row-major fp16 spike stores.
// ---------------------------------------------------------------------------
__global__ void k2_vin() {
  const int id = blockIdx.x * blockDim.x + threadIdx.x;  // 8192
  const int b = id >> 10, n = id & 1023;
  float v = 0.0f;
  unsigned cnt = 0;
  for (int s = 0; s < kS; s++) {
    const float x = g_snn[(size_t)(b * kS + s) * kNin + n];
    const int u0 = s * kT;
#pragma unroll
    for (int t = 0; t < kT; t++) {
      v = fmaf(kAlpha, v, x);
      const bool f = (v >= kThresh);
      const float sp = f ? 1.0f : 0.0f;
      cnt += f;
      v -= sp;
      g_sin[((size_t)(u0 + t) * kB + b) * kNin + n] = __float2half_rn(sp);
    }
  }
  atomicAdd(&g_spk, (unsigned long long)cnt);
}

// ---------------------------------------------------------------------------
// k3: pipelined HMMA GEMM. C[32768 x 1024] = s_in @ (hi + 2^-11 lo)^T.
// Block 128x128, BK=64, 3-stage cp.async, 8 warps (2m x 4n, 64x32 tiles).
// K-loop runs twice (lo plane then hi plane) with a mid-loop acc rescale.
// ---------------------------------------------------------------------------
__global__ void __launch_bounds__(256, 2) k3_gemm() {
  extern __shared__ char smem[];
  const uint32_t sbase = smem_u32(smem);
  const int tid = threadIdx.x, wid = tid >> 5, lane = tid & 31;
  const int wm = wid >> 2, wn = wid & 3;           // 2 x 4 warp grid
  const int m0 = blockIdx.y * BM, n0 = blockIdx.x * BN;

  // --- async stage loader (kv in [0, 32): plane = kv>>4, ktile = kv&15) ---
  auto issue_stage = [&](int kv) {
    if (kv < kKIters) {
      const int stage = kv % STAGES;
      const uint32_t as = sbase + stage * kStageBytes;
      const uint32_t bs = as + BM * BK * 2;
      const int plane = kv >> 4;
      const size_t kt = (size_t)(kv & 15) * BK;
      const char* Ag = (const char*)g_sin + ((size_t)m0 * kNin + kt) * 2;
      const char* Bg = (const char*)g_Wt[plane] + ((size_t)n0 * kNin + kt) * 2;
#pragma unroll
      for (int i = 0; i < 4; i++) {                // A: 128 rows x 8 chunks
        const int cid = tid + i * 256;
        const int r = cid >> 3, c = cid & 7;
        cp_async16(as + swz128((uint32_t)r * 128 + c * 16),
                   Ag + (size_t)r * (kNin * 2) + c * 16);
      }
#pragma unroll
      for (int i = 0; i < 4; i++) {                // B: 128 rows x 8 chunks
        const int cid = tid + i * 256;
        const int r = cid >> 3, c = cid & 7;
        cp_async16(bs + swz128((uint32_t)r * 128 + c * 16),
                   Bg + (size_t)r * (kNin * 2) + c * 16);
      }
    }
    asm volatile("cp.async.commit_group;" ::: "memory");
  };

  issue_stage(0);
  issue_stage(1);

  float acc[4][4][4] = {};
  // precomputed ldmatrix lane addressing
  const int a_row = wm * 64 + (lane & 15);
  const int a_half = lane >> 4;                    // 16B half select
  const int b_row0 = wn * 32 + ((lane >> 4) * 8) + (lane & 7);
  const int b_half = (lane >> 3) & 1;

  for (int kv = 0; kv < kKIters; kv++) {
    asm volatile("cp.async.wait_group 1;" ::: "memory");
    __syncthreads();
    if (kv == kKIters / 2) {                       // lo pass done: rescale
#pragma unroll
      for (int i = 0; i < 4; i++)
#pragma unroll
        for (int j = 0; j < 4; j++)
#pragma unroll
          for (int q = 0; q < 4; q++) acc[i][j][q] *= (1.0f / 2048.0f);
    }
    const int stage = kv % STAGES;
    const uint32_t as = sbase + stage * kStageBytes;
    const uint32_t bs = as + BM * BK * 2;
#pragma unroll
    for (int ks = 0; ks < 4; ks++) {               // 4 x k16 per stage
      uint32_t a[4][4], b[4][2];
#pragma unroll
      for (int i = 0; i < 4; i++)
        ldsm_x4(a[i], as + swz128((uint32_t)(a_row + i * 16) * 128 +
                                  (ks * 2 + a_half) * 16));
#pragma unroll
      for (int jj = 0; jj < 2; jj++) {
        uint32_t r[4];
        ldsm_x4(r, bs + swz128((uint32_t)(b_row0 + jj * 16) * 128 +
                               (ks * 2 + b_half) * 16));
        b[2 * jj][0] = r[0]; b[2 * jj][1] = r[1];
        b[2 * jj + 1][0] = r[2]; b[2 * jj + 1][1] = r[3];
      }
#pragma unroll
      for (int i = 0; i < 4; i++)
#pragma unroll
        for (int j = 0; j < 4; j++) mma16816(acc[i][j], a[i], b[j]);
    }
    issue_stage(kv + 2);
  }

  // --- epilogue: stage through smem for coalesced float4 stores ---
  __syncthreads();
  float* E = reinterpret_cast<float*>(smem);       // 128 x 128 f32 (64 KB)
  const int er = lane >> 2, ec = (lane & 3) * 2;
#pragma unroll
  for (int i = 0; i < 4; i++)
#pragma unroll
    for (int j = 0; j < 4; j++) {
      float* e0 = &E[(size_t)(wm * 64 + i * 16 + er) * BN + wn * 32 + j * 8 + ec];
      e0[0] = acc[i][j][0]; e0[1] = acc[i][j][1];
      float* e1 = e0 + 8 * BN;
      e1[0] = acc[i][j][2]; e1[1] = acc[i][j][3];
    }
  __syncthreads();
#pragma unroll
  for (int q = 0; q < 16; q++) {
    const int idx = tid + q * 256;                 // 4096 float4
    const int r = idx >> 5, c4 = (idx & 31) * 4;
    *reinterpret_cast<float4*>(&g_cur[(size_t)(m0 + r) * kNout + n0 + c4]) =
        *reinterpret_cast<const float4*>(&E[(size_t)r * BN + c4]);
  }
}

// ---------------------------------------------------------------------------
// k4: output LIF, thread per (b, j), 32-deep double-buffered prefetch.
// ---------------------------------------------------------------------------
__global__ void k4_vout() {
  const int id = blockIdx.x * blockDim.x + threadIdx.x;  // 8192
  const int b = id >> 10, j = id & 1023;
  const float* p = &g_cur[(size_t)b * kNout + j];
  const size_t stride = (size_t)kB * kNout;
  float buf[2][kT];
#pragma unroll
  for (int t = 0; t < kT; t++) buf[0][t] = p[(size_t)t * stride];
  float v = 0.0f;
  unsigned cnt = 0;
  for (int s = 0; s < kS; s++) {
    const int cur = s & 1;
    if (s + 1 < kS) {
      const float* q = p + (size_t)(s + 1) * kT * stride;
#pragma unroll
      for (int t = 0; t < kT; t++) buf[cur ^ 1][t] = q[(size_t)t * stride];
    }
    float acc = 0.0f;
#pragma unroll
    for (int t = 0; t < kT; t++) {
      v = fmaf(kAlpha, v, buf[cur][t]);
      const bool f = (v >= kThresh);
      const float sp = f ? 1.0f : 0.0f;
      acc += sp;
      cnt += f;
      v -= sp;
    }
    g_sacc[(size_t)(s * kB + b) * kNout + j] = acc;
  }
  atomicAdd(&g_spk, (unsigned long long)cnt);
}

// ---------------------------------------------------------------------------
// k5: out = spike_acc @ W_out + b_out, permuted store to [b][s][d].
// ---------------------------------------------------------------------------
__global__ void k5_gemm_out(const float* __restrict__ W, const float* __restrict__ bias,
                            float* __restrict__ out, int write_rate) {
  if (write_rate && blockIdx.x == 0 && blockIdx.y == 0 && threadIdx.x == 0) {
    out[(size_t)kB * kS * kD] =
        (float)((double)g_spk / (double)((size_t)kB * kS * (kNin + kNout) * kT));
  }
  __shared__ float As[16][66];
  __shared__ float Bs[16][64];
  const int tid = threadIdx.x;
  const int bm = blockIdx.y * 64, bn = blockIdx.x * 64;
  const int tr = (tid >> 4) * 4, tc = (tid & 15) * 4;
  const int arow = tid >> 2, ak = (tid & 3) * 4;
  const int brow = tid >> 4, bcol = (tid & 15) * 4;

  float acc[4][4] = {};
  for (int kk = 0; kk < kNout; kk += 16) {
    float4 av = *reinterpret_cast<const float4*>(&g_sacc[(size_t)(bm + arow) * kNout + kk + ak]);
    float4 bv = *reinterpret_cast<const float4*>(&W[(size_t)(kk + brow) * kD + bn + bcol]);
    As[ak + 0][arow] = av.x; As[ak + 1][arow] = av.y;
    As[ak + 2][arow] = av.z; As[ak + 3][arow] = av.w;
    *reinterpret_cast<float4*>(&Bs[brow][bcol]) = bv;
    __syncthreads();
#pragma unroll
    for (int k = 0; k < 16; k++) {
      float a[4], b[4];
#pragma unroll
      for (int i = 0; i < 4; i++) a[i] = As[k][tr + i];
#pragma unroll
      for (int j = 0; j < 4; j++) b[j] = Bs[k][tc + j];
#pragma unroll
      for (int i = 0; i < 4; i++)
#pragma unroll
        for (int j = 0; j < 4; j++) acc[i][j] = fmaf(a[i], b[j], acc[i][j]);
    }
    __syncthreads();
  }
#pragma unroll
  for (int i = 0; i < 4; i++) {
    const int m = bm + tr + i;
    const int s = m >> 3;  // rows are m = s*B + b
    const int b = m & 7;
#pragma unroll
    for (int j = 0; j < 4; j++) {
      const int n = bn + tc + j;
      out[((size_t)(b * kS + s)) * kD + n] = acc[i][j] + bias[n];
    }
  }
}

// ---------------------------------------------------------------------------
extern "C" void kernel_launch(void* const* d_in, const int* in_sizes, int n_in,
                              void* d_out, int out_size) {
  const float* emb    = (const float*)d_in[0];
  const float* W_in   = (const float*)d_in[1];
  const float* b_in   = (const float*)d_in[2];
  const float* W_conn = (const float*)d_in[3];
  const float* W_out  = (const float*)d_in[4];
  const float* b_out  = (const float*)d_in[5];
  float* out = (float*)d_out;
  const int write_rate = (out_size > kB * kS * kD) ? 1 : 0;

  static int smem_set = 0;
  if (!smem_set) {
    cudaFuncSetAttribute(k3_gemm, cudaFuncAttributeMaxDynamicSharedMemorySize,
                         kSmemK3);
    smem_set = 1;
  }

  k0_prep<<<dim3(kNout / 32, kNin / 32), dim3(32, 8)>>>(W_conn);
  k1_gemm_in<<<dim3(kNin / 64, (kB * kS) / 64), 256>>>(emb, W_in, b_in);
  k2_vin<<<64, 128>>>();
  k3_gemm<<<dim3(kNout / BN, kM / BM), 256, kSmemK3>>>();
  k4_vout<<<64, 128>>>();
  k5_gemm_out<<<dim3(kD / 64, (kS * kB) / 64), 256>>>(W_out, b_out, out, write_rate);
}

// round 5
// speedup vs baseline: 3.0563x; 1.2607x over previous
#include <cuda_runtime.h>
#include <cuda_fp16.h>
#include <cstdint>

// ---------------------------------------------------------------------------
// SNNEmbeddingModel: B=8, S=128, D=512, N_in=N_out=1024, T=32, alpha=0.9
//
//   k0: W_conn -> fp16 {lo*2^11, hi} planes, transposed to [n][k]
//   k1: snn_input = relu(emb @ W_in + b_in)            fp32 SIMT GEMM (small)
//   k2: input LIF scan -> s_in fp16, row-major [m][k], m = u*8+b
//   k3: I = s_in @ W^T via mma.sync m16n8k16 fp16, cp.async 3-stage pipeline,
//       acc = 2^-11 * (s@lo') + s@hi   (fp32-equivalent weights, 2 passes)
//   k4: output LIF scan over I (register ping-pong prefetch) -> spike_acc
//   k5: out = spike_acc @ W_out + b_out (+ spike_rate scalar)
// ---------------------------------------------------------------------------

namespace {
constexpr float kAlpha  = 0.9f;
constexpr float kThresh = 1.0f;
constexpr int kB = 8, kS = 128, kD = 512, kNin = 1024, kNout = 1024, kT = 32;
constexpr int kM = kS * kT * kB;          // 32768 rows, m = u*8 + b
constexpr int BM = 128, BN = 128, BK = 64, STAGES = 3;
constexpr int kStageBytes = (BM * BK + BN * BK) * 2;     // 32 KB
constexpr int kSmemK3 = STAGES * kStageBytes;            // 96 KB
constexpr int kKIters = 2 * (kNin / BK);                 // 32 (lo pass + hi pass)
}  // namespace

// Scratch (device globals; no allocation allowed).
__device__ float g_snn[(size_t)kB * kS * kNin];                   //   4 MB
__device__ __align__(16) __half g_sin[(size_t)kM * kNin];         //  64 MB
__device__ __align__(16) __half g_Wt[2][(size_t)kNout * kNin];    //   4 MB
__device__ float g_cur[(size_t)kM * kNout];                       // 128 MB
__device__ float g_sacc[(size_t)kS * kB * kNout];                 //   4 MB
__device__ unsigned long long g_spk;

// ------------------------------- helpers ----------------------------------
__device__ __forceinline__ uint32_t smem_u32(const void* p) {
  uint32_t a;
  asm("{ .reg .u64 t; cvta.to.shared.u64 t, %1; cvt.u32.u64 %0, t; }"
      : "=r"(a) : "l"(p));
  return a;
}
__device__ __forceinline__ uint32_t swz128(uint32_t off) {
  return off ^ ((off >> 3) & 0x70);   // 16B-chunk xor within 128B rows
}
__device__ __forceinline__ void cp_async16(uint32_t dst, const void* src) {
  asm volatile("cp.async.cg.shared.global [%0], [%1], 16;"
               :: "r"(dst), "l"(src) : "memory");
}
__device__ __forceinline__ void ldsm_x4(uint32_t* r, uint32_t addr) {
  asm volatile("ldmatrix.sync.aligned.m8n8.x4.shared.b16 {%0,%1,%2,%3}, [%4];"
               : "=r"(r[0]), "=r"(r[1]), "=r"(r[2]), "=r"(r[3]) : "r"(addr));
}
__device__ __forceinline__ void mma16816(float* c, const uint32_t* a,
                                         const uint32_t* b) {
  asm volatile(
      "mma.sync.aligned.m16n8k16.row.col.f32.f16.f16.f32 "
      "{%0,%1,%2,%3}, {%4,%5,%6,%7}, {%8,%9}, {%0,%1,%2,%3};"
      : "+f"(c[0]), "+f"(c[1]), "+f"(c[2]), "+f"(c[3])
      : "r"(a[0]), "r"(a[1]), "r"(a[2]), "r"(a[3]), "r"(b[0]), "r"(b[1]));
}

// ---------------------------------------------------------------------------
// k0: smem-tiled transpose + fp16 {lo*2^11, hi} split of W_conn [k][n].
// ---------------------------------------------------------------------------
__global__ void k0_prep(const float* __restrict__ W) {
  __shared__ float t[32][33];
  const int tx = threadIdx.x, ty = threadIdx.y;  // (32, 8)
  const int n0 = blockIdx.x * 32, k0 = blockIdx.y * 32;
  if (blockIdx.x == 0 && blockIdx.y == 0 && tx == 0 && ty == 0) g_spk = 0ull;
#pragma unroll
  for (int i = ty; i < 32; i += 8)
    t[i][tx] = W[(size_t)(k0 + i) * kNout + n0 + tx];
  __syncthreads();
#pragma unroll
  for (int i = ty; i < 32; i += 8) {
    const int n = n0 + i, k = k0 + tx;
    const float w = t[tx][i];
    const __half hi = __float2half_rn(w);
    const __half lo = __float2half_rn((w - __half2float(hi)) * 2048.0f);
    const size_t off = (size_t)n * kNin + k;
    g_Wt[0][off] = lo;   // pass 0: scaled residual
    g_Wt[1][off] = hi;   // pass 1: main term
  }
}

// ---------------------------------------------------------------------------
// k1: 64x64x16 tiled fp32 GEMM, C = relu(emb @ W_in + b_in). [1024x1024] K=512.
// ---------------------------------------------------------------------------
__global__ void k1_gemm_in(const float* __restrict__ A, const float* __restrict__ W,
                           const float* __restrict__ bias) {
  __shared__ float As[16][66];
  __shared__ float Bs[16][64];
  const int tid = threadIdx.x;
  const int bm = blockIdx.y * 64, bn = blockIdx.x * 64;
  const int tr = (tid >> 4) * 4, tc = (tid & 15) * 4;
  const int arow = tid >> 2, ak = (tid & 3) * 4;
  const int brow = tid >> 4, bcol = (tid & 15) * 4;

  float acc[4][4] = {};
  for (int kk = 0; kk < kD; kk += 16) {
    float4 av = *reinterpret_cast<const float4*>(&A[(size_t)(bm + arow) * kD + kk + ak]);
    float4 bv = *reinterpret_cast<const float4*>(&W[(size_t)(kk + brow) * kNin + bn + bcol]);
    As[ak + 0][arow] = av.x; As[ak + 1][arow] = av.y;
    As[ak + 2][arow] = av.z; As[ak + 3][arow] = av.w;
    *reinterpret_cast<float4*>(&Bs[brow][bcol]) = bv;
    __syncthreads();
#pragma unroll
    for (int k = 0; k < 16; k++) {
      float a[4], b[4];
#pragma unroll
      for (int i = 0; i < 4; i++) a[i] = As[k][tr + i];
#pragma unroll
      for (int j = 0; j < 4; j++) b[j] = Bs[k][tc + j];
#pragma unroll
      for (int i = 0; i < 4; i++)
#pragma unroll
        for (int j = 0; j < 4; j++) acc[i][j] = fmaf(a[i], b[j], acc[i][j]);
    }
    __syncthreads();
  }
#pragma unroll
  for (int i = 0; i < 4; i++)
#pragma unroll
    for (int j = 0; j < 4; j++) {
      const int n = bn + tc + j;
      g_snn[(size_t)(bm + tr + i) * kNin + n] = fmaxf(acc[i][j] + bias[n], 0.0f);
    }
}

// ---------------------------------------------------------------------------
// k2: input LIF. Thread per (b, n); coalesced row-major fp16 spike stores.
// ---------------------------------------------------------------------------
__global__ void k2_vin() {
  const int id = blockIdx.x * blockDim.x + threadIdx.x;  // 8192
  const int b = id >> 10, n = id & 1023;
  float v = 0.0f;
  unsigned cnt = 0;
  for (int s = 0; s < kS; s++) {
    const float x = g_snn[(size_t)(b * kS + s) * kNin + n];
    const int u0 = s * kT;
#pragma unroll
    for (int t = 0; t < kT; t++) {
      v = fmaf(kAlpha, v, x);
      const bool f = (v >= kThresh);
      const float sp = f ? 1.0f : 0.0f;
      cnt += f;
      v -= sp;
      g_sin[((size_t)(u0 + t) * kB + b) * kNin + n] = __float2half_rn(sp);
    }
  }
  atomicAdd(&g_spk, (unsigned long long)cnt);
}

// ---------------------------------------------------------------------------
// k3: pipelined HMMA GEMM. C[32768 x 1024] = s_in @ (hi + 2^-11 lo)^T.
// Block 128x128, BK=64, 3-stage cp.async, 8 warps (2m x 4n, 64x32 tiles).
// K-loop runs twice (lo plane then hi plane) with a mid-loop acc rescale.
// ---------------------------------------------------------------------------
__global__ void __launch_bounds__(256, 2) k3_gemm() {
  extern __shared__ char smem[];
  const uint32_t sbase = smem_u32(smem);
  const int tid = threadIdx.x, wid = tid >> 5, lane = tid & 31;
  const int wm = wid >> 2, wn = wid & 3;           // 2 x 4 warp grid
  const int m0 = blockIdx.y * BM, n0 = blockIdx.x * BN;

  // --- async stage loader (kv in [0, 32): plane = kv>>4, ktile = kv&15) ---
  auto issue_stage = [&](int kv) {
    if (kv < kKIters) {
      const int stage = kv % STAGES;
      const uint32_t as = sbase + stage * kStageBytes;
      const uint32_t bs = as + BM * BK * 2;
      const int plane = kv >> 4;
      const size_t kt = (size_t)(kv & 15) * BK;
      const char* Ag = (const char*)g_sin + ((size_t)m0 * kNin + kt) * 2;
      const char* Bg = (const char*)g_Wt[plane] + ((size_t)n0 * kNin + kt) * 2;
#pragma unroll
      for (int i = 0; i < 4; i++) {                // A: 128 rows x 8 chunks
        const int cid = tid + i * 256;
        const int r = cid >> 3, c = cid & 7;
        cp_async16(as + swz128((uint32_t)r * 128 + c * 16),
                   Ag + (size_t)r * (kNin * 2) + c * 16);
      }
#pragma unroll
      for (int i = 0; i < 4; i++) {                // B: 128 rows x 8 chunks
        const int cid = tid + i * 256;
        const int r = cid >> 3, c = cid & 7;
        cp_async16(bs + swz128((uint32_t)r * 128 + c * 16),
                   Bg + (size_t)r * (kNin * 2) + c * 16);
      }
    }
    asm volatile("cp.async.commit_group;" ::: "memory");
  };

  issue_stage(0);
  issue_stage(1);

  float acc[4][4][4] = {};
  // precomputed ldmatrix lane addressing
  const int a_row = wm * 64 + (lane & 15);
  const int a_half = lane >> 4;                    // 16B half select
  const int b_row0 = wn * 32 + ((lane >> 4) * 8) + (lane & 7);
  const int b_half = (lane >> 3) & 1;

  for (int kv = 0; kv < kKIters; kv++) {
    asm volatile("cp.async.wait_group 1;" ::: "memory");
    __syncthreads();
    if (kv == kKIters / 2) {                       // lo pass done: rescale
#pragma unroll
      for (int i = 0; i < 4; i++)
#pragma unroll
        for (int j = 0; j < 4; j++)
#pragma unroll
          for (int q = 0; q < 4; q++) acc[i][j][q] *= (1.0f / 2048.0f);
    }
    const int stage = kv % STAGES;
    const uint32_t as = sbase + stage * kStageBytes;
    const uint32_t bs = as + BM * BK * 2;
#pragma unroll
    for (int ks = 0; ks < 4; ks++) {               // 4 x k16 per stage
      uint32_t a[4][4], b[4][2];
#pragma unroll
      for (int i = 0; i < 4; i++)
        ldsm_x4(a[i], as + swz128((uint32_t)(a_row + i * 16) * 128 +
                                  (ks * 2 + a_half) * 16));
#pragma unroll
      for (int jj = 0; jj < 2; jj++) {
        uint32_t r[4];
        ldsm_x4(r, bs + swz128((uint32_t)(b_row0 + jj * 16) * 128 +
                               (ks * 2 + b_half) * 16));
        b[2 * jj][0] = r[0]; b[2 * jj][1] = r[1];
        b[2 * jj + 1][0] = r[2]; b[2 * jj + 1][1] = r[3];
      }
#pragma unroll
      for (int i = 0; i < 4; i++)
#pragma unroll
        for (int j = 0; j < 4; j++) mma16816(acc[i][j], a[i], b[j]);
    }
    issue_stage(kv + 2);
  }

  // --- epilogue: stage through smem for coalesced float4 stores ---
  __syncthreads();
  float* E = reinterpret_cast<float*>(smem);       // 128 x 128 f32 (64 KB)
  const int er = lane >> 2, ec = (lane & 3) * 2;
#pragma unroll
  for (int i = 0; i < 4; i++)
#pragma unroll
    for (int j = 0; j < 4; j++) {
      float* e0 = &E[(size_t)(wm * 64 + i * 16 + er) * BN + wn * 32 + j * 8 + ec];
      e0[0] = acc[i][j][0]; e0[1] = acc[i][j][1];
      float* e1 = e0 + 8 * BN;
      e1[0] = acc[i][j][2]; e1[1] = acc[i][j][3];
    }
  __syncthreads();
#pragma unroll
  for (int q = 0; q < 16; q++) {
    const int idx = tid + q * 256;                 // 4096 float4
    const int r = idx >> 5, c4 = (idx & 31) * 4;
    *reinterpret_cast<float4*>(&g_cur[(size_t)(m0 + r) * kNout + n0 + c4]) =
        *reinterpret_cast<const float4*>(&E[(size_t)r * BN + c4]);
  }
}

// ---------------------------------------------------------------------------
// k4: output LIF, thread per (b, j). Register ping-pong prefetch: two
// separate arrays with compile-time indices only (no local-mem demotion),
// s-loop unrolled x2.
// ---------------------------------------------------------------------------
__global__ void k4_vout() {
  const int id = blockIdx.x * blockDim.x + threadIdx.x;  // 8192
  const int b = id >> 10, j = id & 1023;
  const float* p = &g_cur[(size_t)b * kNout + j];
  const size_t stride = (size_t)kB * kNout;              // per step u
  float bufA[kT], bufB[kT];
#pragma unroll
  for (int t = 0; t < kT; t++) bufA[t] = p[(size_t)t * stride];
  float v = 0.0f;
  unsigned cnt = 0;
  for (int s = 0; s < kS; s += 2) {
    // prefetch position s+1 into bufB (independent loads, issued up front)
    const float* q1 = p + (size_t)(s + 1) * kT * stride;
#pragma unroll
    for (int t = 0; t < kT; t++) bufB[t] = q1[(size_t)t * stride];
    float acc = 0.0f;
#pragma unroll
    for (int t = 0; t < kT; t++) {
      v = fmaf(kAlpha, v, bufA[t]);
      const bool f = (v >= kThresh);
      const float sp = f ? 1.0f : 0.0f;
      acc += sp; cnt += f; v -= sp;
    }
    g_sacc[(size_t)(s * kB + b) * kNout + j] = acc;
    // prefetch position s+2 into bufA
    if (s + 2 < kS) {
      const float* q2 = p + (size_t)(s + 2) * kT * stride;
#pragma unroll
      for (int t = 0; t < kT; t++) bufA[t] = q2[(size_t)t * stride];
    }
    acc = 0.0f;
#pragma unroll
    for (int t = 0; t < kT; t++) {
      v = fmaf(kAlpha, v, bufB[t]);
      const bool f = (v >= kThresh);
      const float sp = f ? 1.0f : 0.0f;
      acc += sp; cnt += f; v -= sp;
    }
    g_sacc[(size_t)((s + 1) * kB + b) * kNout + j] = acc;
  }
  atomicAdd(&g_spk, (unsigned long long)cnt);
}

// ---------------------------------------------------------------------------
// k5: out = spike_acc @ W_out + b_out, permuted store to [b][s][d].
// ---------------------------------------------------------------------------
__global__ void k5_gemm_out(const float* __restrict__ W, const float* __restrict__ bias,
                            float* __restrict__ out, int write_rate) {
  if (write_rate && blockIdx.x == 0 && blockIdx.y == 0 && threadIdx.x == 0) {
    out[(size_t)kB * kS * kD] =
        (float)((double)g_spk / (double)((size_t)kB * kS * (kNin + kNout) * kT));
  }
  __shared__ float As[16][66];
  __shared__ float Bs[16][64];
  const int tid = threadIdx.x;
  const int bm = blockIdx.y * 64, bn = blockIdx.x * 64;
  const int tr = (tid >> 4) * 4, tc = (tid & 15) * 4;
  const int arow = tid >> 2, ak = (tid & 3) * 4;
  const int brow = tid >> 4, bcol = (tid & 15) * 4;

  float acc[4][4] = {};
  for (int kk = 0; kk < kNout; kk += 16) {
    float4 av = *reinterpret_cast<const float4*>(&g_sacc[(size_t)(bm + arow) * kNout + kk + ak]);
    float4 bv = *reinterpret_cast<const float4*>(&W[(size_t)(kk + brow) * kD + bn + bcol]);
    As[ak + 0][arow] = av.x; As[ak + 1][arow] = av.y;
    As[ak + 2][arow] = av.z; As[ak + 3][arow] = av.w;
    *reinterpret_cast<float4*>(&Bs[brow][bcol]) = bv;
    __syncthreads();
#pragma unroll
    for (int k = 0; k < 16; k++) {
      float a[4], b[4];
#pragma unroll
      for (int i = 0; i < 4; i++) a[i] = As[k][tr + i];
#pragma unroll
      for (int j = 0; j < 4; j++) b[j] = Bs[k][tc + j];
#pragma unroll
      for (int i = 0; i < 4; i++)
#pragma unroll
        for (int j = 0; j < 4; j++) acc[i][j] = fmaf(a[i], b[j], acc[i][j]);
    }
    __syncthreads();
  }
#pragma unroll
  for (int i = 0; i < 4; i++) {
    const int m = bm + tr + i;
    const int s = m >> 3;  // rows are m = s*B + b
    const int b = m & 7;
#pragma unroll
    for (int j = 0; j < 4; j++) {
      const int n = bn + tc + j;
      out[((size_t)(b * kS + s)) * kD + n] = acc[i][j] + bias[n];
    }
  }
}

// ---------------------------------------------------------------------------
extern "C" void kernel_launch(void* const* d_in, const int* in_sizes, int n_in,
                              void* d_out, int out_size) {
  const float* emb    = (const float*)d_in[0];
  const float* W_in   = (const float*)d_in[1];
  const float* b_in   = (const float*)d_in[2];
  const float* W_conn = (const float*)d_in[3];
  const float* W_out  = (const float*)d_in[4];
  const float* b_out  = (const float*)d_in[5];
  float* out = (float*)d_out;
  const int write_rate = (out_size > kB * kS * kD) ? 1 : 0;

  cudaFuncSetAttribute(k3_gemm, cudaFuncAttributeMaxDynamicSharedMemorySize,
                       kSmemK3);

  k0_prep<<<dim3(kNout / 32, kNin / 32), dim3(32, 8)>>>(W_conn);
  k1_gemm_in<<<dim3(kNin / 64, (kB * kS) / 64), 256>>>(emb, W_in, b_in);
  k2_vin<<<256, 32>>>();
  k3_gemm<<<dim3(kNout / BN, kM / BM), 256, kSmemK3>>>();
  k4_vout<<<256, 32>>>();
  k5_gemm_out<<<dim3(kD / 64, (kS * kB) / 64), 256>>>(W_out, b_out, out, write_rate);
}

// round 6
// speedup vs baseline: 3.4105x; 1.1159x over previous
#include <cuda_runtime.h>
#include <cuda_fp16.h>
#include <cstdint>

// ---------------------------------------------------------------------------
// SNNEmbeddingModel: B=8, S=128, D=512, N_in=N_out=1024, T=32, alpha=0.9
//
//   k0: W_conn -> fp16 {lo*2^11, hi} planes, transposed to [n][k]
//   k1: snn_input = relu(emb @ W_in + b_in)            fp32 SIMT GEMM (small)
//   k2: input LIF scan -> s_in fp16, row-major [m][k], m = u*8+b
//   k3: I = s_in @ W^T via mma.sync m16n8k16 fp16, cp.async 3-stage pipeline
//       (loads issued BEFORE compute each iter), acc = 2^-11*(s@lo') + s@hi
//   k4: output LIF scan over I via cp.async smem ring (4 positions deep)
//   k5: out = spike_acc @ W_out + b_out (+ spike_rate scalar)
// ---------------------------------------------------------------------------

namespace {
constexpr float kAlpha  = 0.9f;
constexpr float kThresh = 1.0f;
constexpr int kB = 8, kS = 128, kD = 512, kNin = 1024, kNout = 1024, kT = 32;
constexpr int kM = kS * kT * kB;          // 32768 rows, m = u*8 + b
constexpr int BM = 128, BN = 128, BK = 64, STAGES = 3;
constexpr int kStageBytes = (BM * BK + BN * BK) * 2;     // 32 KB
constexpr int kSmemK3 = STAGES * kStageBytes;            // 96 KB
constexpr int kKIters = 2 * (kNin / BK);                 // 32 (lo pass + hi pass)
}  // namespace

// Scratch (device globals; no allocation allowed).
__device__ float g_snn[(size_t)kB * kS * kNin];                   //   4 MB
__device__ __align__(16) __half g_sin[(size_t)kM * kNin];         //  64 MB
__device__ __align__(16) __half g_Wt[2][(size_t)kNout * kNin];    //   4 MB
__device__ float g_cur[(size_t)kM * kNout];                       // 128 MB
__device__ float g_sacc[(size_t)kS * kB * kNout];                 //   4 MB
__device__ unsigned long long g_spk;

// ------------------------------- helpers ----------------------------------
__device__ __forceinline__ uint32_t smem_u32(const void* p) {
  uint32_t a;
  asm("{ .reg .u64 t; cvta.to.shared.u64 t, %1; cvt.u32.u64 %0, t; }"
      : "=r"(a) : "l"(p));
  return a;
}
__device__ __forceinline__ uint32_t swz128(uint32_t off) {
  return off ^ ((off >> 3) & 0x70);   // 16B-chunk xor within 128B rows
}
__device__ __forceinline__ void cp_async16(uint32_t dst, const void* src) {
  asm volatile("cp.async.cg.shared.global [%0], [%1], 16;"
               :: "r"(dst), "l"(src) : "memory");
}
__device__ __forceinline__ void ldsm_x4(uint32_t* r, uint32_t addr) {
  asm volatile("ldmatrix.sync.aligned.m8n8.x4.shared.b16 {%0,%1,%2,%3}, [%4];"
               : "=r"(r[0]), "=r"(r[1]), "=r"(r[2]), "=r"(r[3]) : "r"(addr));
}
__device__ __forceinline__ void mma16816(float* c, const uint32_t* a,
                                         const uint32_t* b) {
  asm volatile(
      "mma.sync.aligned.m16n8k16.row.col.f32.f16.f16.f32 "
      "{%0,%1,%2,%3}, {%4,%5,%6,%7}, {%8,%9}, {%0,%1,%2,%3};"
      : "+f"(c[0]), "+f"(c[1]), "+f"(c[2]), "+f"(c[3])
      : "r"(a[0]), "r"(a[1]), "r"(a[2]), "r"(a[3]), "r"(b[0]), "r"(b[1]));
}

// ---------------------------------------------------------------------------
// k0: smem-tiled transpose + fp16 {lo*2^11, hi} split of W_conn [k][n].
// ---------------------------------------------------------------------------
__global__ void k0_prep(const float* __restrict__ W) {
  __shared__ float t[32][33];
  const int tx = threadIdx.x, ty = threadIdx.y;  // (32, 8)
  const int n0 = blockIdx.x * 32, k0 = blockIdx.y * 32;
  if (blockIdx.x == 0 && blockIdx.y == 0 && tx == 0 && ty == 0) g_spk = 0ull;
#pragma unroll
  for (int i = ty; i < 32; i += 8)
    t[i][tx] = W[(size_t)(k0 + i) * kNout + n0 + tx];
  __syncthreads();
#pragma unroll
  for (int i = ty; i < 32; i += 8) {
    const int n = n0 + i, k = k0 + tx;
    const float w = t[tx][i];
    const __half hi = __float2half_rn(w);
    const __half lo = __float2half_rn((w - __half2float(hi)) * 2048.0f);
    const size_t off = (size_t)n * kNin + k;
    g_Wt[0][off] = lo;   // pass 0: scaled residual
    g_Wt[1][off] = hi;   // pass 1: main term
  }
}

// ---------------------------------------------------------------------------
// k1: 64x64x16 tiled fp32 GEMM, C = relu(emb @ W_in + b_in). [1024x1024] K=512.
// ---------------------------------------------------------------------------
__global__ void k1_gemm_in(const float* __restrict__ A, const float* __restrict__ W,
                           const float* __restrict__ bias) {
  __shared__ float As[16][66];
  __shared__ float Bs[16][64];
  const int tid = threadIdx.x;
  const int bm = blockIdx.y * 64, bn = blockIdx.x * 64;
  const int tr = (tid >> 4) * 4, tc = (tid & 15) * 4;
  const int arow = tid >> 2, ak = (tid & 3) * 4;
  const int brow = tid >> 4, bcol = (tid & 15) * 4;

  float acc[4][4] = {};
  for (int kk = 0; kk < kD; kk += 16) {
    float4 av = *reinterpret_cast<const float4*>(&A[(size_t)(bm + arow) * kD + kk + ak]);
    float4 bv = *reinterpret_cast<const float4*>(&W[(size_t)(kk + brow) * kNin + bn + bcol]);
    As[ak + 0][arow] = av.x; As[ak + 1][arow] = av.y;
    As[ak + 2][arow] = av.z; As[ak + 3][arow] = av.w;
    *reinterpret_cast<float4*>(&Bs[brow][bcol]) = bv;
    __syncthreads();
#pragma unroll
    for (int k = 0; k < 16; k++) {
      float a[4], b[4];
#pragma unroll
      for (int i = 0; i < 4; i++) a[i] = As[k][tr + i];
#pragma unroll
      for (int j = 0; j < 4; j++) b[j] = Bs[k][tc + j];
#pragma unroll
      for (int i = 0; i < 4; i++)
#pragma unroll
        for (int j = 0; j < 4; j++) acc[i][j] = fmaf(a[i], b[j], acc[i][j]);
    }
    __syncthreads();
  }
#pragma unroll
  for (int i = 0; i < 4; i++)
#pragma unroll
    for (int j = 0; j < 4; j++) {
      const int n = bn + tc + j;
      g_snn[(size_t)(bm + tr + i) * kNin + n] = fmaxf(acc[i][j] + bias[n], 0.0f);
    }
}

// ---------------------------------------------------------------------------
// k2: input LIF. Thread per (b, n); coalesced row-major fp16 spike stores.
// ---------------------------------------------------------------------------
__global__ void k2_vin() {
  const int id = blockIdx.x * blockDim.x + threadIdx.x;  // 8192
  const int b = id >> 10, n = id & 1023;
  float v = 0.0f;
  unsigned cnt = 0;
  for (int s = 0; s < kS; s++) {
    const float x = g_snn[(size_t)(b * kS + s) * kNin + n];
    const int u0 = s * kT;
#pragma unroll
    for (int t = 0; t < kT; t++) {
      v = fmaf(kAlpha, v, x);
      const bool f = (v >= kThresh);
      const float sp = f ? 1.0f : 0.0f;
      cnt += f;
      v -= sp;
      g_sin[((size_t)(u0 + t) * kB + b) * kNin + n] = __float2half_rn(sp);
    }
  }
  atomicAdd(&g_spk, (unsigned long long)cnt);
}

// ---------------------------------------------------------------------------
// k3: pipelined HMMA GEMM. C[32768 x 1024] = s_in @ (hi + 2^-11 lo)^T.
// Block 128x128, BK=64, 3-stage cp.async, 8 warps (2m x 4n, 64x32 tiles).
// Next stage's loads are issued BEFORE the MMA block each iteration so the
// copy path overlaps tensor work. K-loop runs lo plane then hi plane with a
// mid-loop acc rescale.
// ---------------------------------------------------------------------------
__global__ void __launch_bounds__(256, 2) k3_gemm() {
  extern __shared__ char smem[];
  const uint32_t sbase = smem_u32(smem);
  const int tid = threadIdx.x, wid = tid >> 5, lane = tid & 31;
  const int wm = wid >> 2, wn = wid & 3;           // 2 x 4 warp grid
  const int m0 = blockIdx.y * BM, n0 = blockIdx.x * BN;

  // --- async stage loader (kv in [0, 32): plane = kv>>4, ktile = kv&15) ---
  auto issue_stage = [&](int kv) {
    if (kv < kKIters) {
      const int stage = kv % STAGES;
      const uint32_t as = sbase + stage * kStageBytes;
      const uint32_t bs = as + BM * BK * 2;
      const int plane = kv >> 4;
      const size_t kt = (size_t)(kv & 15) * BK;
      const char* Ag = (const char*)g_sin + ((size_t)m0 * kNin + kt) * 2;
      const char* Bg = (const char*)g_Wt[plane] + ((size_t)n0 * kNin + kt) * 2;
#pragma unroll
      for (int i = 0; i < 4; i++) {                // A: 128 rows x 8 chunks
        const int cid = tid + i * 256;
        const int r = cid >> 3, c = cid & 7;
        cp_async16(as + swz128((uint32_t)r * 128 + c * 16),
                   Ag + (size_t)r * (kNin * 2) + c * 16);
      }
#pragma unroll
      for (int i = 0; i < 4; i++) {                // B: 128 rows x 8 chunks
        const int cid = tid + i * 256;
        const int r = cid >> 3, c = cid & 7;
        cp_async16(bs + swz128((uint32_t)r * 128 + c * 16),
                   Bg + (size_t)r * (kNin * 2) + c * 16);
      }
    }
    asm volatile("cp.async.commit_group;" ::: "memory");
  };

  issue_stage(0);
  issue_stage(1);

  float acc[4][4][4] = {};
  // precomputed ldmatrix lane addressing
  const int a_row = wm * 64 + (lane & 15);
  const int a_half = lane >> 4;                    // 16B half select
  const int b_row0 = wn * 32 + ((lane >> 4) * 8) + (lane & 7);
  const int b_half = (lane >> 3) & 1;

  for (int kv = 0; kv < kKIters; kv++) {
    asm volatile("cp.async.wait_group 1;" ::: "memory");
    __syncthreads();
    // stage (kv+2)%3's previous readers finished at iter kv-1 (guaranteed by
    // the barrier above) -> issue its refill now, overlapping this iter's MMAs.
    issue_stage(kv + 2);
    if (kv == kKIters / 2) {                       // lo pass done: rescale
#pragma unroll
      for (int i = 0; i < 4; i++)
#pragma unroll
        for (int j = 0; j < 4; j++)
#pragma unroll
          for (int q = 0; q < 4; q++) acc[i][j][q] *= (1.0f / 2048.0f);
    }
    const int stage = kv % STAGES;
    const uint32_t as = sbase + stage * kStageBytes;
    const uint32_t bs = as + BM * BK * 2;
#pragma unroll
    for (int ks = 0; ks < 4; ks++) {               // 4 x k16 per stage
      uint32_t a[4][4], b[4][2];
#pragma unroll
      for (int i = 0; i < 4; i++)
        ldsm_x4(a[i], as + swz128((uint32_t)(a_row + i * 16) * 128 +
                                  (ks * 2 + a_half) * 16));
#pragma unroll
      for (int jj = 0; jj < 2; jj++) {
        uint32_t r[4];
        ldsm_x4(r, bs + swz128((uint32_t)(b_row0 + jj * 16) * 128 +
                               (ks * 2 + b_half) * 16));
        b[2 * jj][0] = r[0]; b[2 * jj][1] = r[1];
        b[2 * jj + 1][0] = r[2]; b[2 * jj + 1][1] = r[3];
      }
#pragma unroll
      for (int i = 0; i < 4; i++)
#pragma unroll
        for (int j = 0; j < 4; j++) mma16816(acc[i][j], a[i], b[j]);
    }
  }

  // --- epilogue: stage through smem for coalesced float4 stores ---
  __syncthreads();
  float* E = reinterpret_cast<float*>(smem);       // 128 x 128 f32 (64 KB)
  const int er = lane >> 2, ec = (lane & 3) * 2;
#pragma unroll
  for (int i = 0; i < 4; i++)
#pragma unroll
    for (int j = 0; j < 4; j++) {
      float* e0 = &E[(size_t)(wm * 64 + i * 16 + er) * BN + wn * 32 + j * 8 + ec];
      e0[0] = acc[i][j][0]; e0[1] = acc[i][j][1];
      float* e1 = e0 + 8 * BN;
      e1[0] = acc[i][j][2]; e1[1] = acc[i][j][3];
    }
  __syncthreads();
#pragma unroll
  for (int q = 0; q < 16; q++) {
    const int idx = tid + q * 256;                 // 4096 float4
    const int r = idx >> 5, c4 = (idx & 31) * 4;
    *reinterpret_cast<float4*>(&g_cur[(size_t)(m0 + r) * kNout + n0 + c4]) =
        *reinterpret_cast<const float4*>(&E[(size_t)r * BN + c4]);
  }
}

// ---------------------------------------------------------------------------
// k4: output LIF via cp.async smem ring. Block = 64 threads owning 64 j
// columns of one b; 4-position-deep pipeline (24 KB in flight per CTA)
// decouples DRAM MLP from registers. Grid (16, 8) = 128 CTAs.
// ---------------------------------------------------------------------------
__global__ void __launch_bounds__(64) k4_vout() {
  __shared__ __align__(16) float sbuf[4][kT][64];  // 32 KB ring
  const int tid = threadIdx.x;
  const int b = blockIdx.y;
  const int j0 = blockIdx.x * 64;
  const uint32_t sb = smem_u32(sbuf);

  // prologue: prefetch positions 0..3
#pragma unroll
  for (int s = 0; s < 4; s++) {
#pragma unroll
    for (int q = 0; q < 8; q++) {
      const int c = tid + q * 64;                  // 512 x 16B chunks
      const int t = c >> 4, x = c & 15;
      cp_async16(sb + (uint32_t)(((s * kT + t) * 64) + x * 4) * 4,
                 &g_cur[((size_t)(s * kT + t) * kB + b) * kNout + j0 + x * 4]);
    }
    asm volatile("cp.async.commit_group;" ::: "memory");
  }

  float v = 0.0f;
  unsigned cnt = 0;
  for (int s = 0; s < kS; s++) {
    asm volatile("cp.async.wait_group 3;" ::: "memory");
    __syncthreads();
    const int buf = s & 3;
    float acc = 0.0f;
#pragma unroll
    for (int t = 0; t < kT; t++) {
      const float I = sbuf[buf][t][tid];
      v = fmaf(kAlpha, v, I);
      const bool f = (v >= kThresh);
      const float sp = f ? 1.0f : 0.0f;
      acc += sp; cnt += f; v -= sp;
    }
    g_sacc[(size_t)(s * kB + b) * kNout + j0 + tid] = acc;
    __syncthreads();
    const int sn = s + 4;
    if (sn < kS) {
#pragma unroll
      for (int q = 0; q < 8; q++) {
        const int c = tid + q * 64;
        const int t = c >> 4, x = c & 15;
        cp_async16(sb + (uint32_t)(((buf * kT + t) * 64) + x * 4) * 4,
                   &g_cur[((size_t)(sn * kT + t) * kB + b) * kNout + j0 + x * 4]);
      }
    }
    asm volatile("cp.async.commit_group;" ::: "memory");
  }
  atomicAdd(&g_spk, (unsigned long long)cnt);
}

// ---------------------------------------------------------------------------
// k5: out = spike_acc @ W_out + b_out, permuted store to [b][s][d].
// ---------------------------------------------------------------------------
__global__ void k5_gemm_out(const float* __restrict__ W, const float* __restrict__ bias,
                            float* __restrict__ out, int write_rate) {
  if (write_rate && blockIdx.x == 0 && blockIdx.y == 0 && threadIdx.x == 0) {
    out[(size_t)kB * kS * kD] =
        (float)((double)g_spk / (double)((size_t)kB * kS * (kNin + kNout) * kT));
  }
  __shared__ float As[16][66];
  __shared__ float Bs[16][64];
  const int tid = threadIdx.x;
  const int bm = blockIdx.y * 64, bn = blockIdx.x * 64;
  const int tr = (tid >> 4) * 4, tc = (tid & 15) * 4;
  const int arow = tid >> 2, ak = (tid & 3) * 4;
  const int brow = tid >> 4, bcol = (tid & 15) * 4;

  float acc[4][4] = {};
  for (int kk = 0; kk < kNout; kk += 16) {
    float4 av = *reinterpret_cast<const float4*>(&g_sacc[(size_t)(bm + arow) * kNout + kk + ak]);
    float4 bv = *reinterpret_cast<const float4*>(&W[(size_t)(kk + brow) * kD + bn + bcol]);
    As[ak + 0][arow] = av.x; As[ak + 1][arow] = av.y;
    As[ak + 2][arow] = av.z; As[ak + 3][arow] = av.w;
    *reinterpret_cast<float4*>(&Bs[brow][bcol]) = bv;
    __syncthreads();
#pragma unroll
    for (int k = 0; k < 16; k++) {
      float a[4], b[4];
#pragma unroll
      for (int i = 0; i < 4; i++) a[i] = As[k][tr + i];
#pragma unroll
      for (int j = 0; j < 4; j++) b[j] = Bs[k][tc + j];
#pragma unroll
      for (int i = 0; i < 4; i++)
#pragma unroll
        for (int j = 0; j < 4; j++) acc[i][j] = fmaf(a[i], b[j], acc[i][j]);
    }
    __syncthreads();
  }
#pragma unroll
  for (int i = 0; i < 4; i++) {
    const int m = bm + tr + i;
    const int s = m >> 3;  // rows are m = s*B + b
    const int b = m & 7;
#pragma unroll
    for (int j = 0; j < 4; j++) {
      const int n = bn + tc + j;
      out[((size_t)(b * kS + s)) * kD + n] = acc[i][j] + bias[n];
    }
  }
}

// ---------------------------------------------------------------------------
extern "C" void kernel_launch(void* const* d_in, const int* in_sizes, int n_in,
                              void* d_out, int out_size) {
  const float* emb    = (const float*)d_in[0];
  const float* W_in   = (const float*)d_in[1];
  const float* b_in   = (const float*)d_in[2];
  const float* W_conn = (const float*)d_in[3];
  const float* W_out  = (const float*)d_in[4];
  const float* b_out  = (const float*)d_in[5];
  float* out = (float*)d_out;
  const int write_rate = (out_size > kB * kS * kD) ? 1 : 0;

  cudaFuncSetAttribute(k3_gemm, cudaFuncAttributeMaxDynamicSharedMemorySize,
                       kSmemK3);

  k0_prep<<<dim3(kNout / 32, kNin / 32), dim3(32, 8)>>>(W_conn);
  k1_gemm_in<<<dim3(kNin / 64, (kB * kS) / 64), 256>>>(emb, W_in, b_in);
  k2_vin<<<256, 32>>>();
  k3_gemm<<<dim3(kNout / BN, kM / BM), 256, kSmemK3>>>();
  k4_vout<<<dim3(kNout / 64, kB), 64>>>();
  k5_gemm_out<<<dim3(kD / 64, (kS * kB) / 64), 256>>>(W_out, b_out, out, write_rate);
}

// round 8
// speedup vs baseline: 3.4622x; 1.0151x over previous
#include <cuda_runtime.h>
#include <cuda_fp16.h>
#include <cstdint>

// ---------------------------------------------------------------------------
// SNNEmbeddingModel: B=8, S=128, D=512, N_in=N_out=1024, T=32, alpha=0.9
//
//   k0: W_conn -> fp16 {lo*2^11, hi} planes, transposed to [n][k]
//   k1: snn_input = relu(emb @ W_in + b_in)            fp32 SIMT GEMM (small)
//   k2: input LIF scan -> s_in fp16 (FSEL chain), row-major [m][k]
//   k3: I = s_in @ W^T via mma.sync m16n8k16 fp16, cp.async 3-stage pipeline,
//       acc = 2^-11*(s@lo') + s@hi   (fp32-equivalent weights, 2 passes)
//   k4: output LIF scan over I via 6-deep cp.async smem ring
//       (slot = position % ring — fixed indexing)
//   k5: out = spike_acc @ W_out + b_out (+ spike_rate scalar)
// ---------------------------------------------------------------------------

namespace {
constexpr float kAlpha  = 0.9f;
constexpr float kThresh = 1.0f;
constexpr int kB = 8, kS = 128, kD = 512, kNin = 1024, kNout = 1024, kT = 32;
constexpr int kM = kS * kT * kB;          // 32768 rows, m = u*8 + b
constexpr int BM = 128, BN = 128, BK = 64, STAGES = 3;
constexpr int kStageBytes = (BM * BK + BN * BK) * 2;     // 32 KB
constexpr int kSmemK3 = STAGES * kStageBytes;            // 96 KB
constexpr int kKIters = 2 * (kNin / BK);                 // 32 (lo pass + hi pass)
constexpr int kRing = 6;                                 // k4 ring depth (48 KB)
}  // namespace

// Scratch (device globals; no allocation allowed).
__device__ float g_snn[(size_t)kB * kS * kNin];                   //   4 MB
__device__ __align__(16) __half g_sin[(size_t)kM * kNin];         //  64 MB
__device__ __align__(16) __half g_Wt[2][(size_t)kNout * kNin];    //   4 MB
__device__ float g_cur[(size_t)kM * kNout];                       // 128 MB
__device__ float g_sacc[(size_t)kS * kB * kNout];                 //   4 MB
__device__ unsigned long long g_spk;

// ------------------------------- helpers ----------------------------------
__device__ __forceinline__ uint32_t smem_u32(const void* p) {
  uint32_t a;
  asm("{ .reg .u64 t; cvta.to.shared.u64 t, %1; cvt.u32.u64 %0, t; }"
      : "=r"(a) : "l"(p));
  return a;
}
__device__ __forceinline__ uint32_t swz128(uint32_t off) {
  return off ^ ((off >> 3) & 0x70);   // 16B-chunk xor within 128B rows
}
__device__ __forceinline__ void cp_async16(uint32_t dst, const void* src) {
  asm volatile("cp.async.cg.shared.global [%0], [%1], 16;"
               :: "r"(dst), "l"(src) : "memory");
}
__device__ __forceinline__ void ldsm_x4(uint32_t* r, uint32_t addr) {
  asm volatile("ldmatrix.sync.aligned.m8n8.x4.shared.b16 {%0,%1,%2,%3}, [%4];"
               : "=r"(r[0]), "=r"(r[1]), "=r"(r[2]), "=r"(r[3]) : "r"(addr));
}
__device__ __forceinline__ void mma16816(float* c, const uint32_t* a,
                                         const uint32_t* b) {
  asm volatile(
      "mma.sync.aligned.m16n8k16.row.col.f32.f16.f16.f32 "
      "{%0,%1,%2,%3}, {%4,%5,%6,%7}, {%8,%9}, {%0,%1,%2,%3};"
      : "+f"(c[0]), "+f"(c[1]), "+f"(c[2]), "+f"(c[3])
      : "r"(a[0]), "r"(a[1]), "r"(a[2]), "r"(a[3]), "r"(b[0]), "r"(b[1]));
}

// ---------------------------------------------------------------------------
// k0: smem-tiled transpose + fp16 {lo*2^11, hi} split of W_conn [k][n].
// ---------------------------------------------------------------------------
__global__ void k0_prep(const float* __restrict__ W) {
  __shared__ float t[32][33];
  const int tx = threadIdx.x, ty = threadIdx.y;  // (32, 8)
  const int n0 = blockIdx.x * 32, k0 = blockIdx.y * 32;
  if (blockIdx.x == 0 && blockIdx.y == 0 && tx == 0 && ty == 0) g_spk = 0ull;
#pragma unroll
  for (int i = ty; i < 32; i += 8)
    t[i][tx] = W[(size_t)(k0 + i) * kNout + n0 + tx];
  __syncthreads();
#pragma unroll
  for (int i = ty; i < 32; i += 8) {
    const int n = n0 + i, k = k0 + tx;
    const float w = t[tx][i];
    const __half hi = __float2half_rn(w);
    const __half lo = __float2half_rn((w - __half2float(hi)) * 2048.0f);
    const size_t off = (size_t)n * kNin + k;
    g_Wt[0][off] = lo;   // pass 0: scaled residual
    g_Wt[1][off] = hi;   // pass 1: main term
  }
}

// ---------------------------------------------------------------------------
// k1: 64x64x16 tiled fp32 GEMM, C = relu(emb @ W_in + b_in). [1024x1024] K=512.
// ---------------------------------------------------------------------------
__global__ void k1_gemm_in(const float* __restrict__ A, const float* __restrict__ W,
                           const float* __restrict__ bias) {
  __shared__ float As[16][66];
  __shared__ float Bs[16][64];
  const int tid = threadIdx.x;
  const int bm = blockIdx.y * 64, bn = blockIdx.x * 64;
  const int tr = (tid >> 4) * 4, tc = (tid & 15) * 4;
  const int arow = tid >> 2, ak = (tid & 3) * 4;
  const int brow = tid >> 4, bcol = (tid & 15) * 4;

  float acc[4][4] = {};
  for (int kk = 0; kk < kD; kk += 16) {
    float4 av = *reinterpret_cast<const float4*>(&A[(size_t)(bm + arow) * kD + kk + ak]);
    float4 bv = *reinterpret_cast<const float4*>(&W[(size_t)(kk + brow) * kNin + bn + bcol]);
    As[ak + 0][arow] = av.x; As[ak + 1][arow] = av.y;
    As[ak + 2][arow] = av.z; As[ak + 3][arow] = av.w;
    *reinterpret_cast<float4*>(&Bs[brow][bcol]) = bv;
    __syncthreads();
#pragma unroll
    for (int k = 0; k < 16; k++) {
      float a[4], b[4];
#pragma unroll
      for (int i = 0; i < 4; i++) a[i] = As[k][tr + i];
#pragma unroll
      for (int j = 0; j < 4; j++) b[j] = Bs[k][tc + j];
#pragma unroll
      for (int i = 0; i < 4; i++)
#pragma unroll
        for (int j = 0; j < 4; j++) acc[i][j] = fmaf(a[i], b[j], acc[i][j]);
    }
    __syncthreads();
  }
#pragma unroll
  for (int i = 0; i < 4; i++)
#pragma unroll
    for (int j = 0; j < 4; j++) {
      const int n = bn + tc + j;
      g_snn[(size_t)(bm + tr + i) * kNin + n] = fmaxf(acc[i][j] + bias[n], 0.0f);
    }
}

// ---------------------------------------------------------------------------
// k2: input LIF. Thread per (b, n). Critical chain is FFMA -> FSETP -> FSEL;
// spike value, count and store are off-chain. Arithmetic identical to v-=sp.
// ---------------------------------------------------------------------------
__global__ void k2_vin() {
  const int id = blockIdx.x * blockDim.x + threadIdx.x;  // 8192
  const int b = id >> 10, n = id & 1023;
  float v = 0.0f;
  float total = 0.0f;
  for (int s = 0; s < kS; s++) {
    const float x = g_snn[(size_t)(b * kS + s) * kNin + n];
    const int u0 = s * kT;
#pragma unroll
    for (int t = 0; t < kT; t++) {
      const float vn = fmaf(kAlpha, v, x);
      const float vr = (vn >= kThresh) ? vn - kThresh : vn;  // chain: setp+sel
      const float sp = vn - vr;                              // off-chain: 0 or 1
      total += sp;
      g_sin[((size_t)(u0 + t) * kB + b) * kNin + n] = __float2half_rn(sp);
      v = vr;
    }
  }
  atomicAdd(&g_spk, (unsigned long long)(unsigned)total);
}

// ---------------------------------------------------------------------------
// k3: pipelined HMMA GEMM. C[32768 x 1024] = s_in @ (hi + 2^-11 lo)^T.
// Block 128x128, BK=64, 3-stage cp.async, 8 warps (2m x 4n, 64x32 tiles).
// K-loop runs twice (lo plane then hi plane) with a mid-loop acc rescale.
// (Round-4/5 load ordering: issue_stage AFTER the MMA block — measured faster.)
// ---------------------------------------------------------------------------
__global__ void __launch_bounds__(256, 2) k3_gemm() {
  extern __shared__ char smem[];
  const uint32_t sbase = smem_u32(smem);
  const int tid = threadIdx.x, wid = tid >> 5, lane = tid & 31;
  const int wm = wid >> 2, wn = wid & 3;           // 2 x 4 warp grid
  const int m0 = blockIdx.y * BM, n0 = blockIdx.x * BN;

  // --- async stage loader (kv in [0, 32): plane = kv>>4, ktile = kv&15) ---
  auto issue_stage = [&](int kv) {
    if (kv < kKIters) {
      const int stage = kv % STAGES;
      const uint32_t as = sbase + stage * kStageBytes;
      const uint32_t bs = as + BM * BK * 2;
      const int plane = kv >> 4;
      const size_t kt = (size_t)(kv & 15) * BK;
      const char* Ag = (const char*)g_sin + ((size_t)m0 * kNin + kt) * 2;
      const char* Bg = (const char*)g_Wt[plane] + ((size_t)n0 * kNin + kt) * 2;
#pragma unroll
      for (int i = 0; i < 4; i++) {                // A: 128 rows x 8 chunks
        const int cid = tid + i * 256;
        const int r = cid >> 3, c = cid & 7;
        cp_async16(as + swz128((uint32_t)r * 128 + c * 16),
                   Ag + (size_t)r * (kNin * 2) + c * 16);
      }
#pragma unroll
      for (int i = 0; i < 4; i++) {                // B: 128 rows x 8 chunks
        const int cid = tid + i * 256;
        const int r = cid >> 3, c = cid & 7;
        cp_async16(bs + swz128((uint32_t)r * 128 + c * 16),
                   Bg + (size_t)r * (kNin * 2) + c * 16);
      }
    }
    asm volatile("cp.async.commit_group;" ::: "memory");
  };

  issue_stage(0);
  issue_stage(1);

  float acc[4][4][4] = {};
  // precomputed ldmatrix lane addressing
  const int a_row = wm * 64 + (lane & 15);
  const int a_half = lane >> 4;                    // 16B half select
  const int b_row0 = wn * 32 + ((lane >> 4) * 8) + (lane & 7);
  const int b_half = (lane >> 3) & 1;

  for (int kv = 0; kv < kKIters; kv++) {
    asm volatile("cp.async.wait_group 1;" ::: "memory");
    __syncthreads();
    if (kv == kKIters / 2) {                       // lo pass done: rescale
#pragma unroll
      for (int i = 0; i < 4; i++)
#pragma unroll
        for (int j = 0; j < 4; j++)
#pragma unroll
          for (int q = 0; q < 4; q++) acc[i][j][q] *= (1.0f / 2048.0f);
    }
    const int stage = kv % STAGES;
    const uint32_t as = sbase + stage * kStageBytes;
    const uint32_t bs = as + BM * BK * 2;
#pragma unroll
    for (int ks = 0; ks < 4; ks++) {               // 4 x k16 per stage
      uint32_t a[4][4], b[4][2];
#pragma unroll
      for (int i = 0; i < 4; i++)
        ldsm_x4(a[i], as + swz128((uint32_t)(a_row + i * 16) * 128 +
                                  (ks * 2 + a_half) * 16));
#pragma unroll
      for (int jj = 0; jj < 2; jj++) {
        uint32_t r[4];
        ldsm_x4(r, bs + swz128((uint32_t)(b_row0 + jj * 16) * 128 +
                               (ks * 2 + b_half) * 16));
        b[2 * jj][0] = r[0]; b[2 * jj][1] = r[1];
        b[2 * jj + 1][0] = r[2]; b[2 * jj + 1][1] = r[3];
      }
#pragma unroll
      for (int i = 0; i < 4; i++)
#pragma unroll
        for (int j = 0; j < 4; j++) mma16816(acc[i][j], a[i], b[j]);
    }
    issue_stage(kv + 2);
  }

  // --- epilogue: stage through smem for coalesced float4 stores ---
  __syncthreads();
  float* E = reinterpret_cast<float*>(smem);       // 128 x 128 f32 (64 KB)
  const int er = lane >> 2, ec = (lane & 3) * 2;
#pragma unroll
  for (int i = 0; i < 4; i++)
#pragma unroll
    for (int j = 0; j < 4; j++) {
      float* e0 = &E[(size_t)(wm * 64 + i * 16 + er) * BN + wn * 32 + j * 8 + ec];
      e0[0] = acc[i][j][0]; e0[1] = acc[i][j][1];
      float* e1 = e0 + 8 * BN;
      e1[0] = acc[i][j][2]; e1[1] = acc[i][j][3];
    }
  __syncthreads();
#pragma unroll
  for (int q = 0; q < 16; q++) {
    const int idx = tid + q * 256;                 // 4096 float4
    const int r = idx >> 5, c4 = (idx & 31) * 4;
    *reinterpret_cast<float4*>(&g_cur[(size_t)(m0 + r) * kNout + n0 + c4]) =
        *reinterpret_cast<const float4*>(&E[(size_t)r * BN + c4]);
  }
}

// ---------------------------------------------------------------------------
// k4: output LIF via cp.async smem ring, 6 positions deep (48 KB). Block =
// 64 threads owning 64 j columns of one b. Invariant: position p lives in
// ring slot p % kRing (consumer reads s % kRing; prefetch of position
// s+kRing-1 writes slot (s+kRing-1) % kRing, freed at iteration s-1).
// ---------------------------------------------------------------------------
__global__ void __launch_bounds__(64) k4_vout() {
  __shared__ __align__(16) float sbuf[kRing][kT][64];  // 48 KB ring
  const int tid = threadIdx.x;
  const int b = blockIdx.y;
  const int j0 = blockIdx.x * 64;
  const uint32_t sb = smem_u32(sbuf);

  // prologue: prefetch positions 0..kRing-2 into slots 0..kRing-2
#pragma unroll
  for (int s = 0; s < kRing - 1; s++) {
#pragma unroll
    for (int q = 0; q < 8; q++) {
      const int c = tid + q * 64;                  // 512 x 16B chunks
      const int t = c >> 4, x = c & 15;
      cp_async16(sb + (uint32_t)(((s * kT + t) * 64) + x * 4) * 4,
                 &g_cur[((size_t)(s * kT + t) * kB + b) * kNout + j0 + x * 4]);
    }
    asm volatile("cp.async.commit_group;" ::: "memory");
  }

  float v = 0.0f;
  float total = 0.0f;
  for (int s = 0; s < kS; s++) {
    asm volatile("cp.async.wait_group %0;" :: "n"(kRing - 2) : "memory");
    __syncthreads();
    const int buf = s % kRing;
    float acc = 0.0f;
#pragma unroll
    for (int t = 0; t < kT; t++) {
      const float vn = fmaf(kAlpha, v, sbuf[buf][t][tid]);
      const float vr = (vn >= kThresh) ? vn - kThresh : vn;
      acc += vn - vr;                              // off-chain spike
      v = vr;
    }
    g_sacc[(size_t)(s * kB + b) * kNout + j0 + tid] = acc;
    total += acc;
    __syncthreads();
    const int sn = s + kRing - 1;
    if (sn < kS) {
      const int slot = sn % kRing;                 // FIX: slot follows position
#pragma unroll
      for (int q = 0; q < 8; q++) {
        const int c = tid + q * 64;
        const int t = c >> 4, x = c & 15;
        cp_async16(sb + (uint32_t)(((slot * kT + t) * 64) + x * 4) * 4,
                   &g_cur[((size_t)(sn * kT + t) * kB + b) * kNout + j0 + x * 4]);
      }
    }
    asm volatile("cp.async.commit_group;" ::: "memory");
  }
  atomicAdd(&g_spk, (unsigned long long)(unsigned)total);
}

// ---------------------------------------------------------------------------
// k5: out = spike_acc @ W_out + b_out, permuted store to [b][s][d].
// ---------------------------------------------------------------------------
__global__ void k5_gemm_out(const float* __restrict__ W, const float* __restrict__ bias,
                            float* __restrict__ out, int write_rate) {
  if (write_rate && blockIdx.x == 0 && blockIdx.y == 0 && threadIdx.x == 0) {
    out[(size_t)kB * kS * kD] =
        (float)((double)g_spk / (double)((size_t)kB * kS * (kNin + kNout) * kT));
  }
  __shared__ float As[16][66];
  __shared__ float Bs[16][64];
  const int tid = threadIdx.x;
  const int bm = blockIdx.y * 64, bn = blockIdx.x * 64;
  const int tr = (tid >> 4) * 4, tc = (tid & 15) * 4;
  const int arow = tid >> 2, ak = (tid & 3) * 4;
  const int brow = tid >> 4, bcol = (tid & 15) * 4;

  float acc[4][4] = {};
  for (int kk = 0; kk < kNout; kk += 16) {
    float4 av = *reinterpret_cast<const float4*>(&g_sacc[(size_t)(bm + arow) * kNout + kk + ak]);
    float4 bv = *reinterpret_cast<const float4*>(&W[(size_t)(kk + brow) * kD + bn + bcol]);
    As[ak + 0][arow] = av.x; As[ak + 1][arow] = av.y;
    As[ak + 2][arow] = av.z; As[ak + 3][arow] = av.w;
    *reinterpret_cast<float4*>(&Bs[brow][bcol]) = bv;
    __syncthreads();
#pragma unroll
    for (int k = 0; k < 16; k++) {
      float a[4], b[4];
#pragma unroll
      for (int i = 0; i < 4; i++) a[i] = As[k][tr + i];
#pragma unroll
      for (int j = 0; j < 4; j++) b[j] = Bs[k][tc + j];
#pragma unroll
      for (int i = 0; i < 4; i++)
#pragma unroll
        for (int j = 0; j < 4; j++) acc[i][j] = fmaf(a[i], b[j], acc[i][j]);
    }
    __syncthreads();
  }
#pragma unroll
  for (int i = 0; i < 4; i++) {
    const int m = bm + tr + i;
    const int s = m >> 3;  // rows are m = s*B + b
    const int b = m & 7;
#pragma unroll
    for (int j = 0; j < 4; j++) {
      const int n = bn + tc + j;
      out[((size_t)(b * kS + s)) * kD + n] = acc[i][j] + bias[n];
    }
  }
}

// ---------------------------------------------------------------------------
extern "C" void kernel_launch(void* const* d_in, const int* in_sizes, int n_in,
                              void* d_out, int out_size) {
  const float* emb    = (const float*)d_in[0];
  const float* W_in   = (const float*)d_in[1];
  const float* b_in   = (const float*)d_in[2];
  const float* W_conn = (const float*)d_in[3];
  const float* W_out  = (const float*)d_in[4];
  const float* b_out  = (const float*)d_in[5];
  float* out = (float*)d_out;
  const int write_rate = (out_size > kB * kS * kD) ? 1 : 0;

  cudaFuncSetAttribute(k3_gemm, cudaFuncAttributeMaxDynamicSharedMemorySize,
                       kSmemK3);

  k0_prep<<<dim3(kNout / 32, kNin / 32), dim3(32, 8)>>>(W_conn);
  k1_gemm_in<<<dim3(kNin / 64, (kB * kS) / 64), 256>>>(emb, W_in, b_in);
  k2_vin<<<256, 32>>>();
  k3_gemm<<<dim3(kNout / BN, kM / BM), 256, kSmemK3>>>();
  k4_vout<<<dim3(kNout / 64, kB), 64>>>();
  k5_gemm_out<<<dim3(kD / 64, (kS * kB) / 64), 256>>>(W_out, b_out, out, write_rate);
}

// round 11
// speedup vs baseline: 3.6839x; 1.0640x over previous
#include <cuda_runtime.h>
#include <cuda_fp16.h>
#include <cstdint>

// ---------------------------------------------------------------------------
// SNNEmbeddingModel: B=8, S=128, D=512, N_in=N_out=1024, T=32, alpha=0.9
//
//   k0 : W_conn -> fp16 {hi, lo*2^11} planes, transposed to [n][k]
//   k0c: W_out  -> fp16 {hi, lo*2^11} planes, transposed to [d][k]
//   k1 : snn_input = relu(emb @ W_in + b_in)  fp32 SIMT (proven rounds 1-8)
//   k2 : input LIF scan -> s_in fp16 (FSEL chain), row-major [m][k]
//   k3 : I = s_in @ W^T  HMMA, cp.async 3-stage pipeline, 2 passes
//   k4 : output LIF scan over I via 6-deep cp.async smem ring -> fp16 acc
//   k5h: out = spike_acc @ W_out + b_out  HMMA, 2 passes (+ spike_rate)
//
//   BISECT ROUND: k1h reverted to fp32; k5h kept. Isolates rounds-9/10 bug.
// ---------------------------------------------------------------------------

namespace {
constexpr float kAlpha  = 0.9f;
constexpr float kThresh = 1.0f;
constexpr int kB = 8, kS = 128, kD = 512, kNin = 1024, kNout = 1024, kT = 32;
constexpr int kM = kS * kT * kB;          // 32768 rows, m = u*8 + b
constexpr int BM = 128, BN = 128, BK = 64, STAGES = 3;
constexpr int kStageBytes = (BM * BK + BN * BK) * 2;     // 32 KB
constexpr int kSmemGemm = STAGES * kStageBytes;          // 96 KB
constexpr int kKIters = 2 * (kNin / BK);                 // 32 (lo pass + hi pass)
constexpr int kRing = 6;                                 // k4 ring depth (48 KB)
}  // namespace

// Scratch (device globals; no allocation allowed).
__device__ float g_snn[(size_t)kB * kS * kNin];                   //   4 MB
__device__ __align__(16) __half g_sin[(size_t)kM * kNin];         //  64 MB
__device__ __align__(16) __half g_Wt[2][(size_t)kNout * kNin];    //   4 MB
__device__ __align__(16) __half g_Wout[2][(size_t)kD * kNout];    //   2 MB
__device__ float g_cur[(size_t)kM * kNout];                       // 128 MB
__device__ __align__(16) __half g_sacch[(size_t)kS * kB * kNout]; //   2 MB
__device__ unsigned long long g_spk;

// ------------------------------- helpers ----------------------------------
__device__ __forceinline__ uint32_t smem_u32(const void* p) {
  uint32_t a;
  asm("{ .reg .u64 t; cvta.to.shared.u64 t, %1; cvt.u32.u64 %0, t; }"
      : "=r"(a) : "l"(p));
  return a;
}
__device__ __forceinline__ uint32_t swz128(uint32_t off) {
  return off ^ ((off >> 3) & 0x70);   // 16B-chunk xor within 128B rows
}
__device__ __forceinline__ void cp_async16(uint32_t dst, const void* src) {
  asm volatile("cp.async.cg.shared.global [%0], [%1], 16;"
               :: "r"(dst), "l"(src) : "memory");
}
__device__ __forceinline__ void ldsm_x4(uint32_t* r, uint32_t addr) {
  asm volatile("ldmatrix.sync.aligned.m8n8.x4.shared.b16 {%0,%1,%2,%3}, [%4];"
               : "=r"(r[0]), "=r"(r[1]), "=r"(r[2]), "=r"(r[3]) : "r"(addr));
}
__device__ __forceinline__ void mma16816(float* c, const uint32_t* a,
                                         const uint32_t* b) {
  asm volatile(
      "mma.sync.aligned.m16n8k16.row.col.f32.f16.f16.f32 "
      "{%0,%1,%2,%3}, {%4,%5,%6,%7}, {%8,%9}, {%0,%1,%2,%3};"
      : "+f"(c[0]), "+f"(c[1]), "+f"(c[2]), "+f"(c[3])
      : "r"(a[0]), "r"(a[1]), "r"(a[2]), "r"(a[3]), "r"(b[0]), "r"(b[1]));
}
__device__ __forceinline__ void split16(float w, __half& hi, __half& lo) {
  hi = __float2half_rn(w);
  lo = __float2half_rn((w - __half2float(hi)) * 2048.0f);
}

// ---------------------------------------------------------------------------
// k0: transpose + split W_conn [k][n] -> g_Wt[{hi,lo}][n][k]. Zeroes g_spk.
// ---------------------------------------------------------------------------
__global__ void k0_prep(const float* __restrict__ W) {
  __shared__ float t[32][33];
  const int tx = threadIdx.x, ty = threadIdx.y;  // (32, 8)
  const int n0 = blockIdx.x * 32, k0 = blockIdx.y * 32;
  if (blockIdx.x == 0 && blockIdx.y == 0 && tx == 0 && ty == 0) g_spk = 0ull;
#pragma unroll
  for (int i = ty; i < 32; i += 8)
    t[i][tx] = W[(size_t)(k0 + i) * kNout + n0 + tx];
  __syncthreads();
#pragma unroll
  for (int i = ty; i < 32; i += 8) {
    const int n = n0 + i, k = k0 + tx;
    __half hi, lo;
    split16(t[tx][i], hi, lo);
    const size_t off = (size_t)n * kNin + k;
    g_Wt[0][off] = hi; g_Wt[1][off] = lo;
  }
}

// k0c: transpose + split W_out [1024][512] -> g_Wout[.][d][k], k<1024.
__global__ void k0c_wout(const float* __restrict__ W) {
  __shared__ float t[32][33];
  const int tx = threadIdx.x, ty = threadIdx.y;
  const int d0 = blockIdx.x * 32, k0 = blockIdx.y * 32;
#pragma unroll
  for (int i = ty; i < 32; i += 8)
    t[i][tx] = W[(size_t)(k0 + i) * kD + d0 + tx];
  __syncthreads();
#pragma unroll
  for (int i = ty; i < 32; i += 8) {
    const int d = d0 + i, k = k0 + tx;
    __half hi, lo;
    split16(t[tx][i], hi, lo);
    const size_t off = (size_t)d * kNout + k;
    g_Wout[0][off] = hi; g_Wout[1][off] = lo;
  }
}

// ---------------------------------------------------------------------------
// k1: 64x64x16 tiled fp32 GEMM, C = relu(emb @ W_in + b_in). [1024x1024] K=512.
// (proven rounds 1-8 — input-population path must stay fp32-exact)
// ---------------------------------------------------------------------------
__global__ void k1_gemm_in(const float* __restrict__ A, const float* __restrict__ W,
                           const float* __restrict__ bias) {
  __shared__ float As[16][66];
  __shared__ float Bs[16][64];
  const int tid = threadIdx.x;
  const int bm = blockIdx.y * 64, bn = blockIdx.x * 64;
  const int tr = (tid >> 4) * 4, tc = (tid & 15) * 4;
  const int arow = tid >> 2, ak = (tid & 3) * 4;
  const int brow = tid >> 4, bcol = (tid & 15) * 4;

  float acc[4][4] = {};
  for (int kk = 0; kk < kD; kk += 16) {
    float4 av = *reinterpret_cast<const float4*>(&A[(size_t)(bm + arow) * kD + kk + ak]);
    float4 bv = *reinterpret_cast<const float4*>(&W[(size_t)(kk + brow) * kNin + bn + bcol]);
    As[ak + 0][arow] = av.x; As[ak + 1][arow] = av.y;
    As[ak + 2][arow] = av.z; As[ak + 3][arow] = av.w;
    *reinterpret_cast<float4*>(&Bs[brow][bcol]) = bv;
    __syncthreads();
#pragma unroll
    for (int k = 0; k < 16; k++) {
      float a[4], b[4];
#pragma unroll
      for (int i = 0; i < 4; i++) a[i] = As[k][tr + i];
#pragma unroll
      for (int j = 0; j < 4; j++) b[j] = Bs[k][tc + j];
#pragma unroll
      for (int i = 0; i < 4; i++)
#pragma unroll
        for (int j = 0; j < 4; j++) acc[i][j] = fmaf(a[i], b[j], acc[i][j]);
    }
    __syncthreads();
  }
#pragma unroll
  for (int i = 0; i < 4; i++)
#pragma unroll
    for (int j = 0; j < 4; j++) {
      const int n = bn + tc + j;
      g_snn[(size_t)(bm + tr + i) * kNin + n] = fmaxf(acc[i][j] + bias[n], 0.0f);
    }
}

// ---------------------------------------------------------------------------
// k2: input LIF. Thread per (b, n). FFMA -> FSETP -> FSEL chain.
// ---------------------------------------------------------------------------
__global__ void k2_vin() {
  const int id = blockIdx.x * blockDim.x + threadIdx.x;  // 8192
  const int b = id >> 10, n = id & 1023;
  float v = 0.0f;
  float total = 0.0f;
  for (int s = 0; s < kS; s++) {
    const float x = g_snn[(size_t)(b * kS + s) * kNin + n];
    const int u0 = s * kT;
#pragma unroll
    for (int t = 0; t < kT; t++) {
      const float vn = fmaf(kAlpha, v, x);
      const float vr = (vn >= kThresh) ? vn - kThresh : vn;
      const float sp = vn - vr;
      total += sp;
      g_sin[((size_t)(u0 + t) * kB + b) * kNin + n] = __float2half_rn(sp);
      v = vr;
    }
  }
  atomicAdd(&g_spk, (unsigned long long)(unsigned)total);
}

// ---------------------------------------------------------------------------
// k3: pipelined HMMA GEMM. C[32768 x 1024] = s_in @ (hi + 2^-11 lo)^T.
// (unchanged — measured 317 us, tensor 71%)
// ---------------------------------------------------------------------------
__global__ void __launch_bounds__(256, 2) k3_gemm() {
  extern __shared__ char smem[];
  const uint32_t sbase = smem_u32(smem);
  const int tid = threadIdx.x, wid = tid >> 5, lane = tid & 31;
  const int wm = wid >> 2, wn = wid & 3;
  const int m0 = blockIdx.y * BM, n0 = blockIdx.x * BN;

  auto issue_stage = [&](int kv) {
    if (kv < kKIters) {
      const int stage = kv % STAGES;
      const uint32_t as = sbase + stage * kStageBytes;
      const uint32_t bs = as + BM * BK * 2;
      const int plane = kv >> 4;
      const size_t kt = (size_t)(kv & 15) * BK;
      const char* Ag = (const char*)g_sin + ((size_t)m0 * kNin + kt) * 2;
      const char* Bg = (const char*)(plane ? g_Wt[0] : g_Wt[1]) +
                       ((size_t)n0 * kNin + kt) * 2;
#pragma unroll
      for (int i = 0; i < 4; i++) {
        const int cid = tid + i * 256;
        const int r = cid >> 3, c = cid & 7;
        cp_async16(as + swz128((uint32_t)r * 128 + c * 16),
                   Ag + (size_t)r * (kNin * 2) + c * 16);
      }
#pragma unroll
      for (int i = 0; i < 4; i++) {
        const int cid = tid + i * 256;
        const int r = cid >> 3, c = cid & 7;
        cp_async16(bs + swz128((uint32_t)r * 128 + c * 16),
                   Bg + (size_t)r * (kNin * 2) + c * 16);
      }
    }
    asm volatile("cp.async.commit_group;" ::: "memory");
  };

  issue_stage(0);
  issue_stage(1);

  float acc[4][4][4] = {};
  const int a_row = wm * 64 + (lane & 15);
  const int a_half = lane >> 4;
  const int b_row0 = wn * 32 + ((lane >> 4) * 8) + (lane & 7);
  const int b_half = (lane >> 3) & 1;

  for (int kv = 0; kv < kKIters; kv++) {
    asm volatile("cp.async.wait_group 1;" ::: "memory");
    __syncthreads();
    if (kv == kKIters / 2) {
#pragma unroll
      for (int i = 0; i < 4; i++)
#pragma unroll
        for (int j = 0; j < 4; j++)
#pragma unroll
          for (int q = 0; q < 4; q++) acc[i][j][q] *= (1.0f / 2048.0f);
    }
    const int stage = kv % STAGES;
    const uint32_t as = sbase + stage * kStageBytes;
    const uint32_t bs = as + BM * BK * 2;
#pragma unroll
    for (int ks = 0; ks < 4; ks++) {
      uint32_t a[4][4], b[4][2];
#pragma unroll
      for (int i = 0; i < 4; i++)
        ldsm_x4(a[i], as + swz128((uint32_t)(a_row + i * 16) * 128 +
                                  (ks * 2 + a_half) * 16));
#pragma unroll
      for (int jj = 0; jj < 2; jj++) {
        uint32_t r[4];
        ldsm_x4(r, bs + swz128((uint32_t)(b_row0 + jj * 16) * 128 +
                               (ks * 2 + b_half) * 16));
        b[2 * jj][0] = r[0]; b[2 * jj][1] = r[1];
        b[2 * jj + 1][0] = r[2]; b[2 * jj + 1][1] = r[3];
      }
#pragma unroll
      for (int i = 0; i < 4; i++)
#pragma unroll
        for (int j = 0; j < 4; j++) mma16816(acc[i][j], a[i], b[j]);
    }
    issue_stage(kv + 2);
  }

  __syncthreads();
  float* E = reinterpret_cast<float*>(smem);
  const int er = lane >> 2, ec = (lane & 3) * 2;
#pragma unroll
  for (int i = 0; i < 4; i++)
#pragma unroll
    for (int j = 0; j < 4; j++) {
      float* e0 = &E[(size_t)(wm * 64 + i * 16 + er) * BN + wn * 32 + j * 8 + ec];
      e0[0] = acc[i][j][0]; e0[1] = acc[i][j][1];
      float* e1 = e0 + 8 * BN;
      e1[0] = acc[i][j][2]; e1[1] = acc[i][j][3];
    }
  __syncthreads();
#pragma unroll
  for (int q = 0; q < 16; q++) {
    const int idx = tid + q * 256;
    const int r = idx >> 5, c4 = (idx & 31) * 4;
    *reinterpret_cast<float4*>(&g_cur[(size_t)(m0 + r) * kNout + n0 + c4]) =
        *reinterpret_cast<const float4*>(&E[(size_t)r * BN + c4]);
  }
}

// ---------------------------------------------------------------------------
// k4: output LIF via cp.async smem ring (slot = position % kRing). Stores
// spike_acc as exact fp16 (integers <= 32) for the k5 HMMA.
// ---------------------------------------------------------------------------
__global__ void __launch_bounds__(64) k4_vout() {
  __shared__ __align__(16) float sbuf[kRing][kT][64];  // 48 KB ring
  const int tid = threadIdx.x;
  const int b = blockIdx.y;
  const int j0 = blockIdx.x * 64;
  const uint32_t sb = smem_u32(sbuf);

#pragma unroll
  for (int s = 0; s < kRing - 1; s++) {
#pragma unroll
    for (int q = 0; q < 8; q++) {
      const int c = tid + q * 64;
      const int t = c >> 4, x = c & 15;
      cp_async16(sb + (uint32_t)(((s * kT + t) * 64) + x * 4) * 4,
                 &g_cur[((size_t)(s * kT + t) * kB + b) * kNout + j0 + x * 4]);
    }
    asm volatile("cp.async.commit_group;" ::: "memory");
  }

  float v = 0.0f;
  float total = 0.0f;
  for (int s = 0; s < kS; s++) {
    asm volatile("cp.async.wait_group %0;" :: "n"(kRing - 2) : "memory");
    __syncthreads();
    const int buf = s % kRing;
    float acc = 0.0f;
#pragma unroll
    for (int t = 0; t < kT; t++) {
      const float vn = fmaf(kAlpha, v, sbuf[buf][t][tid]);
      const float vr = (vn >= kThresh) ? vn - kThresh : vn;
      acc += vn - vr;
      v = vr;
    }
    g_sacch[(size_t)(s * kB + b) * kNout + j0 + tid] = __float2half_rn(acc);
    total += acc;
    __syncthreads();
    const int sn = s + kRing - 1;
    if (sn < kS) {
      const int slot = sn % kRing;
#pragma unroll
      for (int q = 0; q < 8; q++) {
        const int c = tid + q * 64;
        const int t = c >> 4, x = c & 15;
        cp_async16(sb + (uint32_t)(((slot * kT + t) * 64) + x * 4) * 4,
                   &g_cur[((size_t)(sn * kT + t) * kB + b) * kNout + j0 + x * 4]);
      }
    }
    asm volatile("cp.async.commit_group;" ::: "memory");
  }
  atomicAdd(&g_spk, (unsigned long long)(unsigned)total);
}

// ---------------------------------------------------------------------------
// k5h: HMMA GEMM. out = spike_acc @ W_out + b_out, permuted store [b][s][d].
// M=1024 (rows s*8+b), N=512, K=1024; lo pass then hi pass (A is exact fp16).
// ---------------------------------------------------------------------------
__global__ void __launch_bounds__(256, 2) k5h_gemm(const float* __restrict__ bias,
                                                   float* __restrict__ out,
                                                   int write_rate) {
  extern __shared__ char smem[];
  const uint32_t sbase = smem_u32(smem);
  const int tid = threadIdx.x, wid = tid >> 5, lane = tid & 31;
  const int wm = wid >> 2, wn = wid & 3;
  const int m0 = blockIdx.y * BM, n0 = blockIdx.x * BN;
  constexpr int IT = 32;

  auto issue_stage = [&](int kv) {
    if (kv < IT) {
      const int stage = kv % STAGES;
      const uint32_t as = sbase + stage * kStageBytes;
      const uint32_t bs = as + BM * BK * 2;
      const size_t kt = (size_t)(kv & 15) * BK;
      const __half* Bp = (kv < 16) ? g_Wout[1] : g_Wout[0];
      const char* Ag = (const char*)(g_sacch + (size_t)m0 * kNout + kt);
      const char* Bg = (const char*)(Bp + (size_t)n0 * kNout + kt);
#pragma unroll
      for (int i = 0; i < 4; i++) {
        const int cid = tid + i * 256;
        const int r = cid >> 3, c = cid & 7;
        cp_async16(as + swz128((uint32_t)r * 128 + c * 16),
                   Ag + (size_t)r * (kNout * 2) + c * 16);
      }
#pragma unroll
      for (int i = 0; i < 4; i++) {
        const int cid = tid + i * 256;
        const int r = cid >> 3, c = cid & 7;
        cp_async16(bs + swz128((uint32_t)r * 128 + c * 16),
                   Bg + (size_t)r * (kNout * 2) + c * 16);
      }
    }
    asm volatile("cp.async.commit_group;" ::: "memory");
  };

  issue_stage(0);
  issue_stage(1);

  float acc[4][4][4] = {};
  const int a_row = wm * 64 + (lane & 15);
  const int a_half = lane >> 4;
  const int b_row0 = wn * 32 + ((lane >> 4) * 8) + (lane & 7);
  const int b_half = (lane >> 3) & 1;

  for (int kv = 0; kv < IT; kv++) {
    asm volatile("cp.async.wait_group 1;" ::: "memory");
    __syncthreads();
    if (kv == 16) {
#pragma unroll
      for (int i = 0; i < 4; i++)
#pragma unroll
        for (int j = 0; j < 4; j++)
#pragma unroll
          for (int q = 0; q < 4; q++) acc[i][j][q] *= (1.0f / 2048.0f);
    }
    const int stage = kv % STAGES;
    const uint32_t as = sbase + stage * kStageBytes;
    const uint32_t bs = as + BM * BK * 2;
#pragma unroll
    for (int ks = 0; ks < 4; ks++) {
      uint32_t a[4][4], b[4][2];
#pragma unroll
      for (int i = 0; i < 4; i++)
        ldsm_x4(a[i], as + swz128((uint32_t)(a_row + i * 16) * 128 +
                                  (ks * 2 + a_half) * 16));
#pragma unroll
      for (int jj = 0; jj < 2; jj++) {
        uint32_t r[4];
        ldsm_x4(r, bs + swz128((uint32_t)(b_row0 + jj * 16) * 128 +
                               (ks * 2 + b_half) * 16));
        b[2 * jj][0] = r[0]; b[2 * jj][1] = r[1];
        b[2 * jj + 1][0] = r[2]; b[2 * jj + 1][1] = r[3];
      }
#pragma unroll
      for (int i = 0; i < 4; i++)
#pragma unroll
        for (int j = 0; j < 4; j++) mma16816(acc[i][j], a[i], b[j]);
    }
    issue_stage(kv + 2);
  }

  __syncthreads();
  float* E = reinterpret_cast<float*>(smem);
  const int er = lane >> 2, ec = (lane & 3) * 2;
#pragma unroll
  for (int i = 0; i < 4; i++)
#pragma unroll
    for (int j = 0; j < 4; j++) {
      float* e0 = &E[(size_t)(wm * 64 + i * 16 + er) * BN + wn * 32 + j * 8 + ec];
      e0[0] = acc[i][j][0]; e0[1] = acc[i][j][1];
      float* e1 = e0 + 8 * BN;
      e1[0] = acc[i][j][2]; e1[1] = acc[i][j][3];
    }
  __syncthreads();
  if (write_rate && blockIdx.x == 0 && blockIdx.y == 0 && tid == 0) {
    out[(size_t)kB * kS * kD] =
        (float)((double)g_spk / (double)((size_t)kB * kS * (kNin + kNout) * kT));
  }
#pragma unroll
  for (int q = 0; q < 16; q++) {
    const int idx = tid + q * 256;
    const int r = idx >> 5, c4 = (idx & 31) * 4;
    const int m = m0 + r;
    const int s = m >> 3, b = m & 7;       // rows are m = s*B + b
    float4 v = *reinterpret_cast<const float4*>(&E[(size_t)r * BN + c4]);
    const float4 bb = *reinterpret_cast<const float4*>(&bias[n0 + c4]);
    v.x += bb.x; v.y += bb.y; v.z += bb.z; v.w += bb.w;
    *reinterpret_cast<float4*>(&out[((size_t)(b * kS + s)) * kD + n0 + c4]) = v;
  }
}

// ---------------------------------------------------------------------------
extern "C" void kernel_launch(void* const* d_in, const int* in_sizes, int n_in,
                              void* d_out, int out_size) {
  const float* emb    = (const float*)d_in[0];
  const float* W_in   = (const float*)d_in[1];
  const float* b_in   = (const float*)d_in[2];
  const float* W_conn = (const float*)d_in[3];
  const float* W_out  = (const float*)d_in[4];
  const float* b_out  = (const float*)d_in[5];
  float* out = (float*)d_out;
  const int write_rate = (out_size > kB * kS * kD) ? 1 : 0;

  cudaFuncSetAttribute(k3_gemm, cudaFuncAttributeMaxDynamicSharedMemorySize, kSmemGemm);
  cudaFuncSetAttribute(k5h_gemm, cudaFuncAttributeMaxDynamicSharedMemorySize, kSmemGemm);

  k0_prep<<<dim3(kNout / 32, kNin / 32), dim3(32, 8)>>>(W_conn);
  k0c_wout<<<dim3(kD / 32, kNout / 32), dim3(32, 8)>>>(W_out);
  k1_gemm_in<<<dim3(kNin / 64, (kB * kS) / 64), 256>>>(emb, W_in, b_in);
  k2_vin<<<256, 32>>>();
  k3_gemm<<<dim3(kNout / BN, kM / BM), 256, kSmemGemm>>>();
  k4_vout<<<dim3(kNout / 64, kB), 64>>>();
  k5h_gemm<<<dim3(kD / BN, (kS * kB) / BM), 256, kSmemGemm>>>(b_out, out, write_rate);
}